// round 3
// baseline (speedup 1.0000x reference)
#include <cuda_runtime.h>
#include <math.h>

#define BATCH 64
#define SEQ   1024
#define D2    1024      // 2*NHID (enc feature dim)
#define DCAT  512       // NHID (cat_emb dim)
#define D3    1536      // 3*NHID (W1 row stride)
#define DA    350
#define DA_PAD 352
#define RR    30
#define MLPD  2048
#define KMLP  46080     // R * 3*NHID
#define ROWS  65536     // B*N
#define NEGV  (-1e9f)
#define KSPLIT 8
#define KCHUNK (KMLP / KSPLIT)  // 5760

// -------- scratch (static device globals; no allocation allowed) --------
__device__ float g_catc[BATCH * DA_PAD];             // W1_cat @ cat_emb  [B, 350]
__device__ float g_s1[23068672];                     // 65536 x 352 (padded)
__device__ float g_s2[BATCH * RR * SEQ];             // logits [B, R, N]
__device__ float g_M[BATCH * RR * D2];               // M_enc  [B, R, 1024]
__device__ float g_BM[BATCH * KMLP];                 // [B, 46080]
__device__ float g_part[KSPLIT * MLPD * BATCH];      // split-K partials

// ======================================================================
// K0: cat contribution  catc[b,a] = sum_d W1[a, 1024+d] * cat_emb[b,d]
// ======================================================================
__global__ void k0_catc(const float* __restrict__ W1, const float* __restrict__ cat) {
    int b = blockIdx.x;
    int warp = threadIdx.x >> 5, lane = threadIdx.x & 31;
    const float* cb = cat + b * DCAT;
    for (int a = warp; a < DA; a += 8) {
        const float* w = W1 + (size_t)a * D3 + D2;
        float s = 0.f;
        for (int d = lane; d < DCAT; d += 32) s += w[d] * cb[d];
        #pragma unroll
        for (int o = 16; o; o >>= 1) s += __shfl_xor_sync(0xffffffffu, s, o);
        if (lane == 0) g_catc[b * DA_PAD + a] = s;
    }
}

// ======================================================================
// K1: s1 = tanh(enc @ W1_encT + catc)   M=65536 N=350(pad 384) K=1024
//     tiles 128x64x16, 256 thr, 8x4 regs
// ======================================================================
__global__ void k1_s1(const float* __restrict__ enc, const float* __restrict__ W1) {
    __shared__ float As[16][128];
    __shared__ float Bs[16][64];
    int t = threadIdx.x;
    int m0 = blockIdx.x * 128;
    int n0 = blockIdx.y * 64;
    int ty = t >> 4, tx = t & 15;
    float acc[8][4];
    #pragma unroll
    for (int i = 0; i < 8; i++)
        #pragma unroll
        for (int j = 0; j < 4; j++) acc[i][j] = 0.f;

    for (int k0 = 0; k0 < D2; k0 += 16) {
        #pragma unroll
        for (int l = 0; l < 2; l++) {
            int idx = t + l * 256;
            int row = idx >> 2, kc = (idx & 3) * 4;
            float4 v = *(const float4*)(enc + (size_t)(m0 + row) * D2 + k0 + kc);
            As[kc + 0][row] = v.x; As[kc + 1][row] = v.y;
            As[kc + 2][row] = v.z; As[kc + 3][row] = v.w;
        }
        {
            int n = t >> 2, kc = (t & 3) * 4;
            float4 v = make_float4(0.f, 0.f, 0.f, 0.f);
            if (n0 + n < DA) v = *(const float4*)(W1 + (size_t)(n0 + n) * D3 + k0 + kc);
            Bs[kc + 0][n] = v.x; Bs[kc + 1][n] = v.y;
            Bs[kc + 2][n] = v.z; Bs[kc + 3][n] = v.w;
        }
        __syncthreads();
        #pragma unroll
        for (int k = 0; k < 16; k++) {
            float a[8], bv[4];
            *(float4*)(a)     = *(const float4*)(&As[k][ty * 8]);
            *(float4*)(a + 4) = *(const float4*)(&As[k][ty * 8 + 4]);
            *(float4*)(bv)    = *(const float4*)(&Bs[k][tx * 4]);
            #pragma unroll
            for (int i = 0; i < 8; i++)
                #pragma unroll
                for (int j = 0; j < 4; j++) acc[i][j] += a[i] * bv[j];
        }
        __syncthreads();
    }
    #pragma unroll
    for (int i = 0; i < 8; i++) {
        int m = m0 + ty * 8 + i;
        int b = m >> 10;
        #pragma unroll
        for (int j = 0; j < 4; j++) {
            int n = n0 + tx * 4 + j;
            if (n < DA)
                g_s1[(size_t)m * DA_PAD + n] = tanhf(acc[i][j] + g_catc[b * DA_PAD + n]);
            else if (n < DA_PAD)
                g_s1[(size_t)m * DA_PAD + n] = 0.f;
        }
    }
}

// ======================================================================
// K2: s2 = s1 @ W2T   M=65536 N=30(pad 32) K=352  -> g_s2[b,r,n]
//     tiles 128x32x32, 256 thr, 4x4 regs
// ======================================================================
__global__ void k2_s2(const float* __restrict__ W2) {
    __shared__ float As[32][128];
    __shared__ float Bs[32][32];
    int t = threadIdx.x;
    int m0 = blockIdx.x * 128;
    int ty = t >> 3, tx = t & 7;   // ty:0..31 (m), tx:0..7 (n)
    float acc[4][4];
    #pragma unroll
    for (int i = 0; i < 4; i++)
        #pragma unroll
        for (int j = 0; j < 4; j++) acc[i][j] = 0.f;

    for (int k0 = 0; k0 < DA_PAD; k0 += 32) {
        #pragma unroll
        for (int l = 0; l < 4; l++) {
            int idx = t + l * 256;
            int row = idx >> 3, kc = (idx & 7) * 4;
            float4 v = *(const float4*)(g_s1 + (size_t)(m0 + row) * DA_PAD + k0 + kc);
            As[kc + 0][row] = v.x; As[kc + 1][row] = v.y;
            As[kc + 2][row] = v.z; As[kc + 3][row] = v.w;
        }
        {
            int r = t >> 3, kc = (t & 7) * 4;
            #pragma unroll
            for (int j = 0; j < 4; j++) {
                int k = k0 + kc + j;
                Bs[kc + j][r] = (r < RR && k < DA) ? W2[r * DA + k] : 0.f;
            }
        }
        __syncthreads();
        #pragma unroll
        for (int k = 0; k < 32; k++) {
            float a[4], bv[4];
            *(float4*)a  = *(const float4*)(&As[k][ty * 4]);
            *(float4*)bv = *(const float4*)(&Bs[k][tx * 4]);
            #pragma unroll
            for (int i = 0; i < 4; i++)
                #pragma unroll
                for (int j = 0; j < 4; j++) acc[i][j] += a[i] * bv[j];
        }
        __syncthreads();
    }
    #pragma unroll
    for (int i = 0; i < 4; i++) {
        int m = m0 + ty * 4 + i;
        int b = m >> 10, npos = m & 1023;
        #pragma unroll
        for (int j = 0; j < 4; j++) {
            int r = tx * 4 + j;
            if (r < RR) g_s2[((size_t)b * RR + r) * SEQ + npos] = acc[i][j];
        }
    }
}

// ======================================================================
// K3: masked softmax over n; writes A into d_out A-region
// ======================================================================
__global__ void k3_softmax(const int* __restrict__ len, float* __restrict__ outA) {
    __shared__ float sred[8];
    int br = blockIdx.x;              // b*RR + r
    int b = br / RR;
    int t = threadIdx.x;              // 256
    int lane = t & 31, warp = t >> 5;
    const float* src = g_s2 + (size_t)br * SEQ;
    int L = len[b];

    float4 v = *(const float4*)(src + t * 4);
    float vv[4] = {v.x, v.y, v.z, v.w};
    #pragma unroll
    for (int j = 0; j < 4; j++) if (t * 4 + j >= L) vv[j] = NEGV;

    float mx = fmaxf(fmaxf(vv[0], vv[1]), fmaxf(vv[2], vv[3]));
    #pragma unroll
    for (int o = 16; o; o >>= 1) mx = fmaxf(mx, __shfl_xor_sync(0xffffffffu, mx, o));
    if (lane == 0) sred[warp] = mx;
    __syncthreads();
    mx = sred[0];
    #pragma unroll
    for (int w = 1; w < 8; w++) mx = fmaxf(mx, sred[w]);

    float e[4], s = 0.f;
    #pragma unroll
    for (int j = 0; j < 4; j++) { e[j] = __expf(vv[j] - mx); s += e[j]; }
    #pragma unroll
    for (int o = 16; o; o >>= 1) s += __shfl_xor_sync(0xffffffffu, s, o);
    __syncthreads();
    if (lane == 0) sred[warp] = s;
    __syncthreads();
    s = 0.f;
    #pragma unroll
    for (int w = 0; w < 8; w++) s += sred[w];
    float inv = 1.f / s;

    float4 o4 = make_float4(e[0] * inv, e[1] * inv, e[2] * inv, e[3] * inv);
    *(float4*)(outA + (size_t)br * SEQ + t * 4) = o4;
}

// ======================================================================
// K4: M_enc[b,r,d] = sum_n A[b,r,n] * enc[b,n,d]
//     grid (8 dtiles, 64 b), nchunk=32, 4r x 4d regs
// ======================================================================
__global__ void k4_mgemm(const float* __restrict__ enc, const float* __restrict__ outA) {
    __shared__ float Ash[32][32];    // [n][r]
    __shared__ float Es[32][128];    // [n][d]
    int t = threadIdx.x;
    int dtile = blockIdx.x, b = blockIdx.y;
    int ty = t >> 5, tx = t & 31;    // ty: r-group (0..7), tx: d-group (0..31)
    const float* Ab = outA + (size_t)b * RR * SEQ;
    const float* Eb = enc + (size_t)b * SEQ * D2 + dtile * 128;
    float acc[4][4];
    #pragma unroll
    for (int i = 0; i < 4; i++)
        #pragma unroll
        for (int j = 0; j < 4; j++) acc[i][j] = 0.f;

    for (int n0 = 0; n0 < SEQ; n0 += 32) {
        {
            int r = t >> 3, nc = (t & 7) * 4;
            float4 v = make_float4(0.f, 0.f, 0.f, 0.f);
            if (r < RR) v = *(const float4*)(Ab + (size_t)r * SEQ + n0 + nc);
            Ash[nc + 0][r] = v.x; Ash[nc + 1][r] = v.y;
            Ash[nc + 2][r] = v.z; Ash[nc + 3][r] = v.w;
        }
        #pragma unroll
        for (int l = 0; l < 4; l++) {
            int idx = t + l * 256;
            int n = idx >> 5, dc = (idx & 31) * 4;
            *(float4*)(&Es[n][dc]) = *(const float4*)(Eb + (size_t)(n0 + n) * D2 + dc);
        }
        __syncthreads();
        #pragma unroll
        for (int n = 0; n < 32; n++) {
            float a[4], e[4];
            *(float4*)a = *(const float4*)(&Ash[n][ty * 4]);
            *(float4*)e = *(const float4*)(&Es[n][tx * 4]);
            #pragma unroll
            for (int i = 0; i < 4; i++)
                #pragma unroll
                for (int j = 0; j < 4; j++) acc[i][j] += a[i] * e[j];
        }
        __syncthreads();
    }
    #pragma unroll
    for (int i = 0; i < 4; i++) {
        int r = ty * 4 + i;
        if (r >= RR) continue;
        #pragma unroll
        for (int j = 0; j < 4; j++) {
            int d = dtile * 128 + tx * 4 + j;
            g_M[((size_t)b * RR + r) * D2 + d] = acc[i][j];
        }
    }
}

// ======================================================================
// K5: assemble BM[b, r*1536 + d]:  d<1024 -> M_enc, else cat_emb (exact,
//     because softmax rows sum to 1)
// ======================================================================
__global__ void k5_bm(const float* __restrict__ cat) {
    size_t idx = ((size_t)blockIdx.x * 256 + threadIdx.x) * 4;
    int b = (int)(idx / KMLP);
    int rem = (int)(idx % KMLP);
    int r = rem / D3, d = rem % D3;
    float4 v;
    if (d < D2) v = *(const float4*)(g_M + ((size_t)b * RR + r) * D2 + d);
    else        v = *(const float4*)(cat + (size_t)b * DCAT + (d - D2));
    *(float4*)(g_BM + idx) = v;
}

// ======================================================================
// K6: split-K GEMM  part[ks, j, b] = sum_{k in split} W_mlp[j,k]*BM[b,k]
//     tiles 128x64x16, grid (16 jtiles, 8 ksplits)
// ======================================================================
__global__ void k6_mlp(const float* __restrict__ Wm) {
    __shared__ float Ws[16][128];
    __shared__ float Bms[16][64];
    int t = threadIdx.x;
    int jtile = blockIdx.x, ks = blockIdx.y;
    int ty = t >> 4, tx = t & 15;
    int kbeg = ks * KCHUNK;
    float acc[8][4];
    #pragma unroll
    for (int i = 0; i < 8; i++)
        #pragma unroll
        for (int j = 0; j < 4; j++) acc[i][j] = 0.f;

    for (int kk = 0; kk < KCHUNK; kk += 16) {
        int k0 = kbeg + kk;
        #pragma unroll
        for (int l = 0; l < 2; l++) {
            int idx = t + l * 256;
            int row = idx >> 2, kc = (idx & 3) * 4;
            float4 v = *(const float4*)(Wm + (size_t)(jtile * 128 + row) * KMLP + k0 + kc);
            Ws[kc + 0][row] = v.x; Ws[kc + 1][row] = v.y;
            Ws[kc + 2][row] = v.z; Ws[kc + 3][row] = v.w;
        }
        {
            int bb = t >> 2, kc = (t & 3) * 4;
            float4 v = *(const float4*)(g_BM + (size_t)bb * KMLP + k0 + kc);
            Bms[kc + 0][bb] = v.x; Bms[kc + 1][bb] = v.y;
            Bms[kc + 2][bb] = v.z; Bms[kc + 3][bb] = v.w;
        }
        __syncthreads();
        #pragma unroll
        for (int k = 0; k < 16; k++) {
            float a[8], bv[4];
            *(float4*)(a)     = *(const float4*)(&Ws[k][ty * 8]);
            *(float4*)(a + 4) = *(const float4*)(&Ws[k][ty * 8 + 4]);
            *(float4*)(bv)    = *(const float4*)(&Bms[k][tx * 4]);
            #pragma unroll
            for (int i = 0; i < 8; i++)
                #pragma unroll
                for (int j = 0; j < 4; j++) acc[i][j] += a[i] * bv[j];
        }
        __syncthreads();
    }
    #pragma unroll
    for (int i = 0; i < 8; i++) {
        int j = jtile * 128 + ty * 8 + i;
        #pragma unroll
        for (int jj = 0; jj < 4; jj++) {
            int b = tx * 4 + jj;
            g_part[((size_t)ks * MLPD + j) * BATCH + b] = acc[i][jj];
        }
    }
}

// ======================================================================
// K7: reduce split-K + bias -> d_out[b*2048 + j]
// ======================================================================
__global__ void k7_reduce(const float* __restrict__ bias, float* __restrict__ out) {
    int idx = blockIdx.x * 256 + threadIdx.x;   // 0 .. 131071
    int j = idx >> 6, b = idx & 63;
    float s = bias[j];
    #pragma unroll
    for (int ks = 0; ks < KSPLIT; ks++)
        s += g_part[((size_t)ks * MLPD + j) * BATCH + b];
    out[(size_t)b * MLPD + j] = s;
}

// ======================================================================
extern "C" void kernel_launch(void* const* d_in, const int* in_sizes, int n_in,
                              void* d_out, int out_size) {
    const float* enc = nullptr;
    const int*   len = nullptr;
    const float* cat = nullptr;
    const float* W1 = nullptr;
    const float* W2 = nullptr;
    const float* Wm = nullptr;
    const float* bm = nullptr;
    for (int i = 0; i < n_in; i++) {
        switch (in_sizes[i]) {
            case 67108864: enc = (const float*)d_in[i]; break;   // [64,1024,1024]
            case 64:       len = (const int*)d_in[i];   break;   // lengths
            case 32768:    cat = (const float*)d_in[i]; break;   // [64,1,512]
            case 537600:   W1  = (const float*)d_in[i]; break;   // [350,1536]
            case 10500:    W2  = (const float*)d_in[i]; break;   // [30,350]
            case 94371840: Wm  = (const float*)d_in[i]; break;   // [2048,46080]
            case 2048:     bm  = (const float*)d_in[i]; break;   // bias
            default: break;                                      // batch_size etc.
        }
    }
    float* outf = (float*)d_out;
    float* outO = outf;                 // [64, 2048]
    float* outA = outf + BATCH * MLPD;  // [64, 30, 1024]

    k0_catc   <<<BATCH, 256>>>(W1, cat);
    k1_s1     <<<dim3(ROWS / 128, 6), 256>>>(enc, W1);
    k2_s2     <<<ROWS / 128, 256>>>(W2);
    k3_softmax<<<BATCH * RR, 256>>>(len, outA);
    k4_mgemm  <<<dim3(8, BATCH), 256>>>(enc, outA);
    k5_bm     <<<(BATCH * KMLP) / (256 * 4), 256>>>(cat);
    k6_mlp    <<<dim3(MLPD / 128, KSPLIT), 256>>>(Wm);
    k7_reduce <<<(BATCH * MLPD) / 256, 256>>>(bm, outO);
}

// round 5
// speedup vs baseline: 1.9453x; 1.9453x over previous
#include <cuda_runtime.h>
#include <cuda_bf16.h>
#include <math.h>
#include <stdint.h>

#define BATCH 64
#define SEQ   1024
#define D2    1024
#define DCAT  512
#define D3    1536
#define DA    350
#define DA_PAD 352
#define NW1   384      // W1 bf16 padded rows
#define RR    30
#define MLPD  2048
#define KMLP  46080
#define ROWS  65536
#define NEGV  (-1e9f)
#define KSPLIT 8
#define KCHUNK (KMLP / KSPLIT)   // 5760

// ---------------- scratch ----------------
__device__ float g_catc[BATCH * DA_PAD];          // zero-init; [350,352) stay 0
__device__ float g_s1[(size_t)ROWS * DA_PAD];
__device__ float g_s2[BATCH * RR * SEQ];
__device__ float g_M[BATCH * RR * D2];
__device__ float g_part[KSPLIT * MLPD * BATCH];
__device__ __nv_bfloat16 g_W1h[NW1 * D2];
__device__ __nv_bfloat16 g_W1l[NW1 * D2];
__device__ __nv_bfloat16 g_BMh[BATCH * KMLP];
__device__ __nv_bfloat16 g_BMl[BATCH * KMLP];

// ---------------- helpers ----------------
__device__ __forceinline__ uint32_t smem_u32(const void* p) {
    uint32_t r;
    asm("{ .reg .u64 t; cvta.to.shared.u64 t, %1; cvt.u32.u64 %0, t; }" : "=r"(r) : "l"(p));
    return r;
}
__device__ __forceinline__ void ldsm4(uint32_t* r, uint32_t addr) {
    asm volatile("ldmatrix.sync.aligned.m8n8.x4.shared.b16 {%0,%1,%2,%3}, [%4];"
                 : "=r"(r[0]), "=r"(r[1]), "=r"(r[2]), "=r"(r[3]) : "r"(addr));
}
__device__ __forceinline__ void mma16816(float* c, const uint32_t* a, const uint32_t* b) {
    asm volatile(
        "mma.sync.aligned.m16n8k16.row.col.f32.bf16.bf16.f32 "
        "{%0,%1,%2,%3}, {%4,%5,%6,%7}, {%8,%9}, {%0,%1,%2,%3};"
        : "+f"(c[0]), "+f"(c[1]), "+f"(c[2]), "+f"(c[3])
        : "r"(a[0]), "r"(a[1]), "r"(a[2]), "r"(a[3]), "r"(b[0]), "r"(b[1]));
}
__device__ __forceinline__ void split_bf(float a, uint32_t& h, uint32_t& l) {
    __nv_bfloat16 hh = __float2bfloat16_rn(a);
    __nv_bfloat16 ll = __float2bfloat16_rn(a - __bfloat162float(hh));
    h = (uint32_t)__bfloat16_as_ushort(hh);
    l = (uint32_t)__bfloat16_as_ushort(ll);
}
__device__ __forceinline__ uint2 pack2(uint32_t h0, uint32_t h1, uint32_t h2, uint32_t h3) {
    return make_uint2((h1 << 16) | h0, (h3 << 16) | h2);
}

// ======================================================================
// K0: catc[b,a] = W1_cat[a,:] . cat_emb[b,:]
// ======================================================================
__global__ void k0_catc(const float* __restrict__ W1, const float* __restrict__ cat) {
    int b = blockIdx.x;
    int warp = threadIdx.x >> 5, lane = threadIdx.x & 31;
    const float* cb = cat + b * DCAT;
    for (int a = warp; a < DA; a += 8) {
        const float* w = W1 + (size_t)a * D3 + D2;
        float s = 0.f;
        for (int d = lane; d < DCAT; d += 32) s += w[d] * cb[d];
        #pragma unroll
        for (int o = 16; o; o >>= 1) s += __shfl_xor_sync(0xffffffffu, s, o);
        if (lane == 0) g_catc[b * DA_PAD + a] = s;
    }
}

// ======================================================================
// K0b: W1 enc-part -> bf16 hi/lo, [384][1024], rows >= 350 zeroed
// ======================================================================
__global__ void k0b_w1(const float* __restrict__ W1) {
    int i = blockIdx.x * 256 + threadIdx.x;   // < 384*1024
    int row = i >> 10, k = i & 1023;
    float v = (row < DA) ? W1[(size_t)row * D3 + k] : 0.f;
    uint32_t h, l;
    split_bf(v, h, l);
    g_W1h[i] = __ushort_as_bfloat16((uint16_t)h);
    g_W1l[i] = __ushort_as_bfloat16((uint16_t)l);
}

// ======================================================================
// K1: split-bf16 mma.sync GEMM  s1 = tanh(enc @ W1encT + catc)
//     CTA tile 128(M) x 128(N), K chunks of 64. grid (3 ntile, 512 mtile)
//     smem: Ah 16K | Al 16K | Bh 16K | Bl 16K  (XOR-swizzled 128B rows)
// ======================================================================
#define K1_AH 0
#define K1_AL 16384
#define K1_BH 32768
#define K1_BL 49152
#define K1_SMEM 65536

__global__ void __launch_bounds__(256, 1) k1_s1(const float* __restrict__ enc) {
    extern __shared__ __align__(16) char sm[];
    uint32_t sb = smem_u32(sm);
    int t = threadIdx.x;
    int lane = t & 31, wid = t >> 5;
    int n0g = blockIdx.x * 128;
    int m0 = blockIdx.y * 128;
    int wm = (wid >> 2) * 64;        // warp M offset in tile
    int wn = (wid & 3) * 32;         // warp N offset in tile

    float c[4][4][4];
    #pragma unroll
    for (int i = 0; i < 4; i++)
        #pragma unroll
        for (int j = 0; j < 4; j++)
            #pragma unroll
            for (int q = 0; q < 4; q++) c[i][j][q] = 0.f;

    int arow_l = lane & 15;
    int acol_l = (lane >> 4) * 16;                       // bytes
    int brow_l = (lane & 7) + ((lane >> 4) << 3);
    int bcol_l = ((lane >> 3) & 1) * 16;                 // bytes

    for (int ch = 0; ch < 16; ch++) {
        int k0 = ch * 64;
        __syncthreads();
        // A: 128 x 64 fp32 -> bf16 hi/lo (8 float4 per thread)
        #pragma unroll
        for (int li = 0; li < 8; li++) {
            int idx = t + li * 256;
            int row = idx >> 4, seg = idx & 15;
            float4 v = *(const float4*)(enc + (size_t)(m0 + row) * D2 + k0 + seg * 4);
            uint32_t h0, h1, h2, h3, l0, l1, l2, l3;
            split_bf(v.x, h0, l0); split_bf(v.y, h1, l1);
            split_bf(v.z, h2, l2); split_bf(v.w, h3, l3);
            uint32_t byte = row * 128 + ((seg * 8) ^ ((row & 7) << 4));
            *(uint2*)(sm + K1_AH + byte) = pack2(h0, h1, h2, h3);
            *(uint2*)(sm + K1_AL + byte) = pack2(l0, l1, l2, l3);
        }
        // B: 128 x 64 bf16 hi/lo from g_W1h/l (4 uint4 per thread each)
        #pragma unroll
        for (int li = 0; li < 4; li++) {
            int idx = t + li * 256;
            int row = idx >> 3, seg = idx & 7;
            uint32_t byte = row * 128 + ((seg * 16) ^ ((row & 7) << 4));
            size_t g = ((size_t)(n0g + row) << 10) + k0 + seg * 8;
            *(uint4*)(sm + K1_BH + byte) = *(const uint4*)(g_W1h + g);
            *(uint4*)(sm + K1_BL + byte) = *(const uint4*)(g_W1l + g);
        }
        __syncthreads();

        #pragma unroll
        for (int ks = 0; ks < 4; ks++) {
            int kb = ks * 32;                            // byte offset within row
            uint32_t ah[4][4], al[4][4], bh[2][4], bl[2][4];
            #pragma unroll
            for (int mi = 0; mi < 4; mi++) {
                int row = wm + mi * 16 + arow_l;
                uint32_t off = row * 128 + ((kb + acol_l) ^ ((row & 7) << 4));
                ldsm4(ah[mi], sb + K1_AH + off);
                ldsm4(al[mi], sb + K1_AL + off);
            }
            #pragma unroll
            for (int q = 0; q < 2; q++) {
                int row = wn + q * 16 + brow_l;
                uint32_t off = row * 128 + ((kb + bcol_l) ^ ((row & 7) << 4));
                ldsm4(bh[q], sb + K1_BH + off);
                ldsm4(bl[q], sb + K1_BL + off);
            }
            #pragma unroll
            for (int mi = 0; mi < 4; mi++)
                #pragma unroll
                for (int j = 0; j < 4; j++) {
                    const uint32_t* bhp = &bh[j >> 1][(j & 1) * 2];
                    const uint32_t* blp = &bl[j >> 1][(j & 1) * 2];
                    mma16816(c[mi][j], ah[mi], bhp);
                    mma16816(c[mi][j], ah[mi], blp);
                    mma16816(c[mi][j], al[mi], bhp);
                }
        }
    }

    // epilogue: tanh(c + catc) -> g_s1
    int b = m0 >> 10;
    #pragma unroll
    for (int mi = 0; mi < 4; mi++) {
        int mrow = m0 + wm + mi * 16 + (lane >> 2);
        #pragma unroll
        for (int j = 0; j < 4; j++) {
            int nb = n0g + wn + j * 8 + (lane & 3) * 2;
            if (nb < DA_PAD) {
                float cc0 = g_catc[b * DA_PAD + nb];
                float cc1 = g_catc[b * DA_PAD + nb + 1];
                float2 v0 = make_float2(tanhf(c[mi][j][0] + cc0), tanhf(c[mi][j][1] + cc1));
                float2 v1 = make_float2(tanhf(c[mi][j][2] + cc0), tanhf(c[mi][j][3] + cc1));
                *(float2*)(g_s1 + (size_t)mrow * DA_PAD + nb) = v0;
                *(float2*)(g_s1 + (size_t)(mrow + 8) * DA_PAD + nb) = v1;
            }
        }
    }
}

// ======================================================================
// K2: s2 = s1 @ W2T  (SIMT)
// ======================================================================
__global__ void k2_s2(const float* __restrict__ W2) {
    __shared__ float As[32][128];
    __shared__ float Bs[32][32];
    int t = threadIdx.x;
    int m0 = blockIdx.x * 128;
    int ty = t >> 3, tx = t & 7;
    float acc[4][4];
    #pragma unroll
    for (int i = 0; i < 4; i++)
        #pragma unroll
        for (int j = 0; j < 4; j++) acc[i][j] = 0.f;

    for (int k0 = 0; k0 < DA_PAD; k0 += 32) {
        #pragma unroll
        for (int li = 0; li < 4; li++) {
            int idx = t + li * 256;
            int row = idx >> 3, kc = (idx & 7) * 4;
            float4 v = *(const float4*)(g_s1 + (size_t)(m0 + row) * DA_PAD + k0 + kc);
            As[kc + 0][row] = v.x; As[kc + 1][row] = v.y;
            As[kc + 2][row] = v.z; As[kc + 3][row] = v.w;
        }
        {
            int r = t >> 3, kc = (t & 7) * 4;
            #pragma unroll
            for (int j = 0; j < 4; j++) {
                int k = k0 + kc + j;
                Bs[kc + j][r] = (r < RR && k < DA) ? W2[r * DA + k] : 0.f;
            }
        }
        __syncthreads();
        #pragma unroll
        for (int k = 0; k < 32; k++) {
            float a[4], bv[4];
            *(float4*)a  = *(const float4*)(&As[k][ty * 4]);
            *(float4*)bv = *(const float4*)(&Bs[k][tx * 4]);
            #pragma unroll
            for (int i = 0; i < 4; i++)
                #pragma unroll
                for (int j = 0; j < 4; j++) acc[i][j] += a[i] * bv[j];
        }
        __syncthreads();
    }
    #pragma unroll
    for (int i = 0; i < 4; i++) {
        int m = m0 + ty * 4 + i;
        int b = m >> 10, npos = m & 1023;
        #pragma unroll
        for (int j = 0; j < 4; j++) {
            int r = tx * 4 + j;
            if (r < RR) g_s2[((size_t)b * RR + r) * SEQ + npos] = acc[i][j];
        }
    }
}

// ======================================================================
// K3: masked softmax; writes A into d_out
// ======================================================================
__global__ void k3_softmax(const int* __restrict__ len, float* __restrict__ outA) {
    __shared__ float sred[8];
    int br = blockIdx.x;
    int b = br / RR;
    int t = threadIdx.x;
    int lane = t & 31, warp = t >> 5;
    const float* src = g_s2 + (size_t)br * SEQ;
    int L = len[b];

    float4 v = *(const float4*)(src + t * 4);
    float vv[4] = {v.x, v.y, v.z, v.w};
    #pragma unroll
    for (int j = 0; j < 4; j++) if (t * 4 + j >= L) vv[j] = NEGV;

    float mx = fmaxf(fmaxf(vv[0], vv[1]), fmaxf(vv[2], vv[3]));
    #pragma unroll
    for (int o = 16; o; o >>= 1) mx = fmaxf(mx, __shfl_xor_sync(0xffffffffu, mx, o));
    if (lane == 0) sred[warp] = mx;
    __syncthreads();
    mx = sred[0];
    #pragma unroll
    for (int w = 1; w < 8; w++) mx = fmaxf(mx, sred[w]);

    float e[4], s = 0.f;
    #pragma unroll
    for (int j = 0; j < 4; j++) { e[j] = __expf(vv[j] - mx); s += e[j]; }
    #pragma unroll
    for (int o = 16; o; o >>= 1) s += __shfl_xor_sync(0xffffffffu, s, o);
    __syncthreads();
    if (lane == 0) sred[warp] = s;
    __syncthreads();
    s = 0.f;
    #pragma unroll
    for (int w = 0; w < 8; w++) s += sred[w];
    float inv = 1.f / s;

    *(float4*)(outA + (size_t)br * SEQ + t * 4) =
        make_float4(e[0] * inv, e[1] * inv, e[2] * inv, e[3] * inv);
}

// ======================================================================
// K4: M_enc[b,r,d] = sum_n A[b,r,n] * enc[b,n,d]  (SIMT)
// ======================================================================
__global__ void k4_mgemm(const float* __restrict__ enc, const float* __restrict__ outA) {
    __shared__ float Ash[32][32];
    __shared__ float Es[32][128];
    int t = threadIdx.x;
    int dtile = blockIdx.x, b = blockIdx.y;
    int ty = t >> 5, tx = t & 31;
    const float* Ab = outA + (size_t)b * RR * SEQ;
    const float* Eb = enc + (size_t)b * SEQ * D2 + dtile * 128;
    float acc[4][4];
    #pragma unroll
    for (int i = 0; i < 4; i++)
        #pragma unroll
        for (int j = 0; j < 4; j++) acc[i][j] = 0.f;

    for (int n0 = 0; n0 < SEQ; n0 += 32) {
        {
            int r = t >> 3, nc = (t & 7) * 4;
            float4 v = make_float4(0.f, 0.f, 0.f, 0.f);
            if (r < RR) v = *(const float4*)(Ab + (size_t)r * SEQ + n0 + nc);
            Ash[nc + 0][r] = v.x; Ash[nc + 1][r] = v.y;
            Ash[nc + 2][r] = v.z; Ash[nc + 3][r] = v.w;
        }
        #pragma unroll
        for (int li = 0; li < 4; li++) {
            int idx = t + li * 256;
            int n = idx >> 5, dc = (idx & 31) * 4;
            *(float4*)(&Es[n][dc]) = *(const float4*)(Eb + (size_t)(n0 + n) * D2 + dc);
        }
        __syncthreads();
        #pragma unroll
        for (int n = 0; n < 32; n++) {
            float a[4], e[4];
            *(float4*)a = *(const float4*)(&Ash[n][ty * 4]);
            *(float4*)e = *(const float4*)(&Es[n][tx * 4]);
            #pragma unroll
            for (int i = 0; i < 4; i++)
                #pragma unroll
                for (int j = 0; j < 4; j++) acc[i][j] += a[i] * e[j];
        }
        __syncthreads();
    }
    #pragma unroll
    for (int i = 0; i < 4; i++) {
        int r = ty * 4 + i;
        if (r >= RR) continue;
        #pragma unroll
        for (int j = 0; j < 4; j++) {
            int d = dtile * 128 + tx * 4 + j;
            g_M[((size_t)b * RR + r) * D2 + d] = acc[i][j];
        }
    }
}

// ======================================================================
// K5: BM[b, r*1536+d] -> bf16 hi/lo (cat part exact: softmax rows sum to 1)
// ======================================================================
__global__ void k5_bm(const float* __restrict__ cat) {
    size_t idx = ((size_t)blockIdx.x * 256 + threadIdx.x) * 4;
    int b = (int)(idx / KMLP);
    int rem = (int)(idx % KMLP);
    int r = rem / D3, d = rem % D3;
    float4 v;
    if (d < D2) v = *(const float4*)(g_M + ((size_t)b * RR + r) * D2 + d);
    else        v = *(const float4*)(cat + (size_t)b * DCAT + (d - D2));
    uint32_t h0, h1, h2, h3, l0, l1, l2, l3;
    split_bf(v.x, h0, l0); split_bf(v.y, h1, l1);
    split_bf(v.z, h2, l2); split_bf(v.w, h3, l3);
    *(uint2*)(g_BMh + idx) = pack2(h0, h1, h2, h3);
    *(uint2*)(g_BMl + idx) = pack2(l0, l1, l2, l3);
}

// ======================================================================
// K6: split-bf16 mma.sync split-K GEMM  part[ks] = Wm-chunk @ BM-chunkT
//     CTA tile 128(j) x 64(b), grid (16 jtiles, 8 ksplits)
//     smem: Wh 16K | Wl 16K | Bh 8K | Bl 8K = 48K
// ======================================================================
#define K6_WH 0
#define K6_WL 16384
#define K6_BH 32768
#define K6_BL 40960
#define K6_SMEM 49152

__global__ void __launch_bounds__(256, 1) k6_mlp(const float* __restrict__ Wm) {
    extern __shared__ __align__(16) char sm[];
    uint32_t sb = smem_u32(sm);
    int t = threadIdx.x;
    int lane = t & 31, wid = t >> 5;
    int j0 = blockIdx.x * 128;
    int ks = blockIdx.y;
    int kbeg = ks * KCHUNK;
    int wj = (wid >> 2) * 64;
    int wb = (wid & 3) * 16;

    float c[4][2][4];
    #pragma unroll
    for (int i = 0; i < 4; i++)
        #pragma unroll
        for (int j = 0; j < 2; j++)
            #pragma unroll
            for (int q = 0; q < 4; q++) c[i][j][q] = 0.f;

    int arow_l = lane & 15;
    int acol_l = (lane >> 4) * 16;
    int brow_l = (lane & 7) + ((lane >> 4) << 3);
    int bcol_l = ((lane >> 3) & 1) * 16;

    for (int ch = 0; ch < KCHUNK / 64; ch++) {   // 90 chunks
        int k0 = kbeg + ch * 64;
        __syncthreads();
        // Wm: 128 x 64 fp32 -> bf16 hi/lo
        #pragma unroll
        for (int li = 0; li < 8; li++) {
            int idx = t + li * 256;
            int row = idx >> 4, seg = idx & 15;
            float4 v = *(const float4*)(Wm + (size_t)(j0 + row) * KMLP + k0 + seg * 4);
            uint32_t h0, h1, h2, h3, l0, l1, l2, l3;
            split_bf(v.x, h0, l0); split_bf(v.y, h1, l1);
            split_bf(v.z, h2, l2); split_bf(v.w, h3, l3);
            uint32_t byte = row * 128 + ((seg * 8) ^ ((row & 7) << 4));
            *(uint2*)(sm + K6_WH + byte) = pack2(h0, h1, h2, h3);
            *(uint2*)(sm + K6_WL + byte) = pack2(l0, l1, l2, l3);
        }
        // BM: 64 x 64 bf16 hi/lo (2 uint4 per thread each)
        #pragma unroll
        for (int li = 0; li < 2; li++) {
            int idx = t + li * 256;
            int row = idx >> 3, seg = idx & 7;
            uint32_t byte = row * 128 + ((seg * 16) ^ ((row & 7) << 4));
            size_t g = (size_t)row * KMLP + k0 + seg * 8;
            *(uint4*)(sm + K6_BH + byte) = *(const uint4*)(g_BMh + g);
            *(uint4*)(sm + K6_BL + byte) = *(const uint4*)(g_BMl + g);
        }
        __syncthreads();

        #pragma unroll
        for (int ksp = 0; ksp < 4; ksp++) {
            int kb = ksp * 32;
            uint32_t ah[4][4], al[4][4], bh[4], bl[4];
            #pragma unroll
            for (int mi = 0; mi < 4; mi++) {
                int row = wj + mi * 16 + arow_l;
                uint32_t off = row * 128 + ((kb + acol_l) ^ ((row & 7) << 4));
                ldsm4(ah[mi], sb + K6_WH + off);
                ldsm4(al[mi], sb + K6_WL + off);
            }
            {
                int row = wb + brow_l;
                uint32_t off = row * 128 + ((kb + bcol_l) ^ ((row & 7) << 4));
                ldsm4(bh, sb + K6_BH + off);
                ldsm4(bl, sb + K6_BL + off);
            }
            #pragma unroll
            for (int mi = 0; mi < 4; mi++)
                #pragma unroll
                for (int j = 0; j < 2; j++) {
                    const uint32_t* bhp = &bh[j * 2];
                    const uint32_t* blp = &bl[j * 2];
                    mma16816(c[mi][j], ah[mi], bhp);
                    mma16816(c[mi][j], ah[mi], blp);
                    mma16816(c[mi][j], al[mi], bhp);
                }
        }
    }

    // epilogue -> g_part[ks][j][b]
    #pragma unroll
    for (int mi = 0; mi < 4; mi++) {
        int jr = j0 + wj + mi * 16 + (lane >> 2);
        #pragma unroll
        for (int j = 0; j < 2; j++) {
            int bc = wb + j * 8 + (lane & 3) * 2;
            float* d0 = g_part + ((size_t)ks * MLPD + jr) * BATCH + bc;
            float* d1 = g_part + ((size_t)ks * MLPD + jr + 8) * BATCH + bc;
            d0[0] = c[mi][j][0]; d0[1] = c[mi][j][1];
            d1[0] = c[mi][j][2]; d1[1] = c[mi][j][3];
        }
    }
}

// ======================================================================
// K7: reduce split-K + bias -> d_out
// ======================================================================
__global__ void k7_reduce(const float* __restrict__ bias, float* __restrict__ out) {
    int idx = blockIdx.x * 256 + threadIdx.x;
    int j = idx >> 6, b = idx & 63;
    float s = bias[j];
    #pragma unroll
    for (int ks = 0; ks < KSPLIT; ks++)
        s += g_part[((size_t)ks * MLPD + j) * BATCH + b];
    out[(size_t)b * MLPD + j] = s;
}

// ======================================================================
extern "C" void kernel_launch(void* const* d_in, const int* in_sizes, int n_in,
                              void* d_out, int out_size) {
    const float* enc = nullptr;
    const int*   len = nullptr;
    const float* cat = nullptr;
    const float* W1 = nullptr;
    const float* W2 = nullptr;
    const float* Wm = nullptr;
    const float* bm = nullptr;
    for (int i = 0; i < n_in; i++) {
        switch (in_sizes[i]) {
            case 67108864: enc = (const float*)d_in[i]; break;
            case 64:       len = (const int*)d_in[i];   break;
            case 32768:    cat = (const float*)d_in[i]; break;
            case 537600:   W1  = (const float*)d_in[i]; break;
            case 10500:    W2  = (const float*)d_in[i]; break;
            case 94371840: Wm  = (const float*)d_in[i]; break;
            case 2048:     bm  = (const float*)d_in[i]; break;
            default: break;
        }
    }
    float* outf = (float*)d_out;
    float* outO = outf;
    float* outA = outf + BATCH * MLPD;

    cudaFuncSetAttribute(k1_s1, cudaFuncAttributeMaxDynamicSharedMemorySize, K1_SMEM);
    cudaFuncSetAttribute(k6_mlp, cudaFuncAttributeMaxDynamicSharedMemorySize, K6_SMEM);

    k0_catc   <<<BATCH, 256>>>(W1, cat);
    k0b_w1    <<<(NW1 * D2) / 256, 256>>>(W1);
    k1_s1     <<<dim3(3, 512), 256, K1_SMEM>>>(enc);
    k2_s2     <<<ROWS / 128, 256>>>(W2);
    k3_softmax<<<BATCH * RR, 256>>>(len, outA);
    k4_mgemm  <<<dim3(8, BATCH), 256>>>(enc, outA);
    k5_bm     <<<(BATCH * KMLP) / (256 * 4), 256>>>(cat);
    k6_mlp    <<<dim3(MLPD / 128, KSPLIT), 256, K6_SMEM>>>(Wm);
    k7_reduce <<<(BATCH * MLPD) / 256, 256>>>(bm, outO);
}

// round 6
// speedup vs baseline: 2.2757x; 1.1698x over previous
#include <cuda_runtime.h>
#include <cuda_bf16.h>
#include <math.h>
#include <stdint.h>

#define BATCH 64
#define SEQ   1024
#define D2    1024
#define DCAT  512
#define D3    1536
#define DA    350
#define DA_PAD 352
#define NW1   384
#define RR    30
#define MLPD  2048
#define KMLP  46080
#define ROWS  65536
#define NEGV  (-1e9f)
#define KSPLIT 9
#define KCHUNK 5120            // KMLP / 9
#define NCH6   80              // KCHUNK / 64

// ---------------- scratch ----------------
__device__ float g_catc[BATCH * DA_PAD];
__device__ float g_s2[BATCH * RR * SEQ];
__device__ float g_part[KSPLIT * MLPD * BATCH];
__device__ __align__(128) __nv_bfloat16 g_W1h[NW1 * D2];
__device__ __align__(128) __nv_bfloat16 g_W1l[NW1 * D2];
__device__ __align__(128) __nv_bfloat16 g_BMh[BATCH * KMLP];
__device__ __align__(128) __nv_bfloat16 g_BMl[BATCH * KMLP];

// ---------------- helpers ----------------
__device__ __forceinline__ uint32_t smem_u32(const void* p) {
    uint32_t r;
    asm("{ .reg .u64 t; cvta.to.shared.u64 t, %1; cvt.u32.u64 %0, t; }" : "=r"(r) : "l"(p));
    return r;
}
__device__ __forceinline__ void ldsm4(uint32_t* r, uint32_t addr) {
    asm volatile("ldmatrix.sync.aligned.m8n8.x4.shared.b16 {%0,%1,%2,%3}, [%4];"
                 : "=r"(r[0]), "=r"(r[1]), "=r"(r[2]), "=r"(r[3]) : "r"(addr));
}
__device__ __forceinline__ void mma16816(float* c, const uint32_t* a, const uint32_t* b) {
    asm volatile(
        "mma.sync.aligned.m16n8k16.row.col.f32.bf16.bf16.f32 "
        "{%0,%1,%2,%3}, {%4,%5,%6,%7}, {%8,%9}, {%0,%1,%2,%3};"
        : "+f"(c[0]), "+f"(c[1]), "+f"(c[2]), "+f"(c[3])
        : "r"(a[0]), "r"(a[1]), "r"(a[2]), "r"(a[3]), "r"(b[0]), "r"(b[1]));
}
__device__ __forceinline__ void cpasync16(uint32_t dst, const void* src) {
    asm volatile("cp.async.cg.shared.global [%0], [%1], 16;" :: "r"(dst), "l"(src));
}
__device__ __forceinline__ void cpcommit() { asm volatile("cp.async.commit_group;"); }
__device__ __forceinline__ void cpwait0()  { asm volatile("cp.async.wait_group 0;"); }

__device__ __forceinline__ void split_bf(float a, uint32_t& h, uint32_t& l) {
    __nv_bfloat16 hh = __float2bfloat16_rn(a);
    __nv_bfloat16 ll = __float2bfloat16_rn(a - __bfloat162float(hh));
    h = (uint32_t)__bfloat16_as_ushort(hh);
    l = (uint32_t)__bfloat16_as_ushort(ll);
}
__device__ __forceinline__ uint2 pack2(uint32_t h0, uint32_t h1, uint32_t h2, uint32_t h3) {
    return make_uint2((h1 << 16) | h0, (h3 << 16) | h2);
}

// ======================================================================
// K0: catc[b,a] = W1_cat[a,:] . cat_emb[b,:]
// ======================================================================
__global__ void k0_catc(const float* __restrict__ W1, const float* __restrict__ cat) {
    int b = blockIdx.x;
    int warp = threadIdx.x >> 5, lane = threadIdx.x & 31;
    const float* cb = cat + b * DCAT;
    for (int a = warp; a < DA; a += 8) {
        const float* w = W1 + (size_t)a * D3 + D2;
        float s = 0.f;
        for (int d = lane; d < DCAT; d += 32) s += w[d] * cb[d];
        #pragma unroll
        for (int o = 16; o; o >>= 1) s += __shfl_xor_sync(0xffffffffu, s, o);
        if (lane == 0) g_catc[b * DA_PAD + a] = s;
    }
}

// ======================================================================
// K0b: W1 enc-part -> bf16 hi/lo, [384][1024], rows >= 350 zeroed
// ======================================================================
__global__ void k0b_w1(const float* __restrict__ W1) {
    int i = blockIdx.x * 256 + threadIdx.x;
    int row = i >> 10, k = i & 1023;
    float v = (row < DA) ? W1[(size_t)row * D3 + k] : 0.f;
    uint32_t h, l;
    split_bf(v, h, l);
    g_W1h[i] = __ushort_as_bfloat16((uint16_t)h);
    g_W1l[i] = __ushort_as_bfloat16((uint16_t)l);
}

// ======================================================================
// K1: split-bf16 mma.sync GEMM, tile 64(M) x 384(N), K chunks of 32,
//     double-buffered (cp.async B, reg-prefetch A), fused s2 epilogue.
//     grid 1024, 256 thr (8 warps: 2m x 4n, warp tile 32x96).
// ======================================================================
#define K1_STG   57344
#define K1_AH    0
#define K1_AL    4096
#define K1_BH    8192
#define K1_BL    32768
#define K1_SMEM  114688

__global__ void __launch_bounds__(256, 1) k1_s1s2(
    const float* __restrict__ enc,
    const float* __restrict__ W2)
{
    extern __shared__ __align__(128) char sm[];
    uint32_t sb = smem_u32(sm);
    int t = threadIdx.x;
    int lane = t & 31, wid = t >> 5;
    int m0 = blockIdx.x * 64;
    int b = m0 >> 10;
    int wm = (wid >> 2) * 32;          // warp M offset (0/32)
    int wn = (wid & 3) * 96;           // warp N offset

    float c[2][12][4];
    #pragma unroll
    for (int i = 0; i < 2; i++)
        #pragma unroll
        for (int j = 0; j < 12; j++)
            #pragma unroll
            for (int q = 0; q < 4; q++) c[i][j][q] = 0.f;

    // A conversion mapping: r = t>>2 (64 rows), chunk16 = t&3 (16B = 8 bf16)
    int ar = t >> 2, ac = t & 3;
    const float* aptr = enc + (size_t)(m0 + ar) * D2 + ac * 8;
    uint32_t a_sts = (uint32_t)(ar * 64 + ((ac ^ ((ar >> 1) & 3)) << 4));

    float4 pa0, pa1;
    // ---- prologue: B chunk0 via cp.async, A chunk0 via regs ----
    #pragma unroll
    for (int i = 0; i < 6; i++) {
        int idx = t + i * 256;
        int n = idx >> 2, ch = idx & 3;
        uint32_t doff = (uint32_t)(n * 64 + ((ch ^ ((n >> 1) & 3)) << 4));
        const __nv_bfloat16* s = g_W1h + (size_t)n * D2 + ch * 8;
        const __nv_bfloat16* sl = g_W1l + (size_t)n * D2 + ch * 8;
        cpasync16(sb + K1_BH + doff, s);
        cpasync16(sb + K1_BL + doff, sl);
    }
    cpcommit();
    pa0 = *(const float4*)(aptr);
    pa1 = *(const float4*)(aptr + 4);
    {
        uint32_t h[8], l[8];
        split_bf(pa0.x, h[0], l[0]); split_bf(pa0.y, h[1], l[1]);
        split_bf(pa0.z, h[2], l[2]); split_bf(pa0.w, h[3], l[3]);
        split_bf(pa1.x, h[4], l[4]); split_bf(pa1.y, h[5], l[5]);
        split_bf(pa1.z, h[6], l[6]); split_bf(pa1.w, h[7], l[7]);
        *(uint4*)(sm + K1_AH + a_sts) = make_uint4((h[1]<<16)|h[0], (h[3]<<16)|h[2], (h[5]<<16)|h[4], (h[7]<<16)|h[6]);
        *(uint4*)(sm + K1_AL + a_sts) = make_uint4((l[1]<<16)|l[0], (l[3]<<16)|l[2], (l[5]<<16)|l[4], (l[7]<<16)|l[6]);
    }

    for (int cch = 0; cch < 32; cch++) {
        int s = cch & 1;
        uint32_t stg = (uint32_t)(s * K1_STG);
        cpwait0();
        __syncthreads();
        if (cch < 31) {
            uint32_t stg1 = (uint32_t)((s ^ 1) * K1_STG);
            int k0n = (cch + 1) * 32;
            #pragma unroll
            for (int i = 0; i < 6; i++) {
                int idx = t + i * 256;
                int n = idx >> 2, ch = idx & 3;
                uint32_t doff = (uint32_t)(n * 64 + ((ch ^ ((n >> 1) & 3)) << 4));
                cpasync16(sb + stg1 + K1_BH + doff, g_W1h + (size_t)n * D2 + k0n + ch * 8);
                cpasync16(sb + stg1 + K1_BL + doff, g_W1l + (size_t)n * D2 + k0n + ch * 8);
            }
            cpcommit();
            pa0 = *(const float4*)(aptr + k0n);
            pa1 = *(const float4*)(aptr + k0n + 4);
        }
        // ---- MMA on stage s ----
        #pragma unroll
        for (int kstep = 0; kstep < 2; kstep++) {
            uint32_t ah[2][4], al[2][4];
            #pragma unroll
            for (int mi = 0; mi < 2; mi++) {
                int r = wm + mi * 16 + (lane & 15);
                int ch = kstep * 2 + (lane >> 4);
                uint32_t off = (uint32_t)(r * 64 + ((ch ^ ((r >> 1) & 3)) << 4));
                ldsm4(ah[mi], sb + stg + K1_AH + off);
                ldsm4(al[mi], sb + stg + K1_AL + off);
            }
            #pragma unroll
            for (int q = 0; q < 6; q++) {
                uint32_t bh[4], bl[4];
                int n = wn + q * 16 + (lane & 7) + ((lane >> 4) << 3);
                int ch = kstep * 2 + ((lane >> 3) & 1);
                uint32_t off = (uint32_t)(n * 64 + ((ch ^ ((n >> 1) & 3)) << 4));
                ldsm4(bh, sb + stg + K1_BH + off);
                ldsm4(bl, sb + stg + K1_BL + off);
                #pragma unroll
                for (int mi = 0; mi < 2; mi++)
                    #pragma unroll
                    for (int j = 0; j < 2; j++) {
                        mma16816(c[mi][q * 2 + j], ah[mi], &bh[j * 2]);
                        mma16816(c[mi][q * 2 + j], ah[mi], &bl[j * 2]);
                        mma16816(c[mi][q * 2 + j], al[mi], &bh[j * 2]);
                    }
            }
        }
        if (cch < 31) {
            uint32_t stg1 = (uint32_t)((s ^ 1) * K1_STG);
            uint32_t h[8], l[8];
            split_bf(pa0.x, h[0], l[0]); split_bf(pa0.y, h[1], l[1]);
            split_bf(pa0.z, h[2], l[2]); split_bf(pa0.w, h[3], l[3]);
            split_bf(pa1.x, h[4], l[4]); split_bf(pa1.y, h[5], l[5]);
            split_bf(pa1.z, h[6], l[6]); split_bf(pa1.w, h[7], l[7]);
            *(uint4*)(sm + stg1 + K1_AH + a_sts) = make_uint4((h[1]<<16)|h[0], (h[3]<<16)|h[2], (h[5]<<16)|h[4], (h[7]<<16)|h[6]);
            *(uint4*)(sm + stg1 + K1_AL + a_sts) = make_uint4((l[1]<<16)|l[0], (l[3]<<16)|l[2], (l[5]<<16)|l[4], (l[7]<<16)|l[6]);
        }
    }

    // ---- fused epilogue: s2 = tanh(c + catc) @ W2^T ----
    __syncthreads();
    float* W2s  = (float*)(sm);              // [384][32]
    float* catcs = (float*)(sm + 49152);     // [384]
    float* S    = (float*)(sm + 50688);      // [64][202]
    for (int idx = t; idx < 30 * 384; idx += 256) {
        int r = idx / 384, n = idx - r * 384;
        W2s[n * 32 + r] = (n < DA) ? W2[r * DA + n] : 0.f;
    }
    for (int i = t; i < 384; i += 256)
        catcs[i] = (i < DA) ? g_catc[b * DA_PAD + i] : 0.f;
    __syncthreads();

    float s2acc[8];
    #pragma unroll
    for (int rr = 0; rr < 8; rr++) s2acc[rr] = 0.f;
    int ml = t >> 2, rcol = t & 3;

    #pragma unroll
    for (int p = 0; p < 2; p++) {
        if (((wid & 3) >> 1) == p) {
            #pragma unroll
            for (int mi = 0; mi < 2; mi++) {
                int lr = wm + mi * 16 + (lane >> 2);
                #pragma unroll
                for (int cj = 0; cj < 12; cj++) {
                    int ng = wn + cj * 8 + (lane & 3) * 2;
                    int nl = ng - p * 192;
                    float cc0 = catcs[ng], cc1 = catcs[ng + 1];
                    *(float2*)&S[lr * 202 + nl] =
                        make_float2(tanhf(c[mi][cj][0] + cc0), tanhf(c[mi][cj][1] + cc1));
                    *(float2*)&S[(lr + 8) * 202 + nl] =
                        make_float2(tanhf(c[mi][cj][2] + cc0), tanhf(c[mi][cj][3] + cc1));
                }
            }
        }
        __syncthreads();
        const float* Sp = S + ml * 202;
        const float* Wp = W2s + p * 192 * 32 + rcol * 8;
        #pragma unroll 4
        for (int n = 0; n < 192; n++) {
            float a = Sp[n];
            float4 w0 = *(const float4*)(Wp + n * 32);
            float4 w1 = *(const float4*)(Wp + n * 32 + 4);
            s2acc[0] += a * w0.x; s2acc[1] += a * w0.y;
            s2acc[2] += a * w0.z; s2acc[3] += a * w0.w;
            s2acc[4] += a * w1.x; s2acc[5] += a * w1.y;
            s2acc[6] += a * w1.z; s2acc[7] += a * w1.w;
        }
        __syncthreads();
    }
    int npos = (m0 + ml) & 1023;
    #pragma unroll
    for (int rr = 0; rr < 8; rr++) {
        int r = rcol * 8 + rr;
        if (r < RR) g_s2[((size_t)b * RR + r) * SEQ + npos] = s2acc[rr];
    }
}

// ======================================================================
// K3: masked softmax; writes A into d_out
// ======================================================================
__global__ void k3_softmax(const int* __restrict__ len, float* __restrict__ outA) {
    __shared__ float sred[8];
    int br = blockIdx.x;
    int b = br / RR;
    int t = threadIdx.x;
    int lane = t & 31, warp = t >> 5;
    const float* src = g_s2 + (size_t)br * SEQ;
    int L = len[b];

    float4 v = *(const float4*)(src + t * 4);
    float vv[4] = {v.x, v.y, v.z, v.w};
    #pragma unroll
    for (int j = 0; j < 4; j++) if (t * 4 + j >= L) vv[j] = NEGV;

    float mx = fmaxf(fmaxf(vv[0], vv[1]), fmaxf(vv[2], vv[3]));
    #pragma unroll
    for (int o = 16; o; o >>= 1) mx = fmaxf(mx, __shfl_xor_sync(0xffffffffu, mx, o));
    if (lane == 0) sred[warp] = mx;
    __syncthreads();
    mx = sred[0];
    #pragma unroll
    for (int w = 1; w < 8; w++) mx = fmaxf(mx, sred[w]);

    float e[4], s = 0.f;
    #pragma unroll
    for (int j = 0; j < 4; j++) { e[j] = __expf(vv[j] - mx); s += e[j]; }
    #pragma unroll
    for (int o = 16; o; o >>= 1) s += __shfl_xor_sync(0xffffffffu, s, o);
    __syncthreads();
    if (lane == 0) sred[warp] = s;
    __syncthreads();
    s = 0.f;
    #pragma unroll
    for (int w = 0; w < 8; w++) s += sred[w];
    float inv = 1.f / s;

    *(float4*)(outA + (size_t)br * SEQ + t * 4) =
        make_float4(e[0] * inv, e[1] * inv, e[2] * inv, e[3] * inv);
}

// ======================================================================
// K4: M_enc = A @ enc, reg-prefetched; writes BM bf16 hi/lo directly
// ======================================================================
__global__ void k4_mgemm(const float* __restrict__ enc, const float* __restrict__ outA) {
    __shared__ float Ash[32][32];
    __shared__ float Es[32][128];
    int t = threadIdx.x;
    int dtile = blockIdx.x, b = blockIdx.y;
    int ty = t >> 5, tx = t & 31;
    const float* Ab = outA + (size_t)b * RR * SEQ;
    const float* Eb = enc + (size_t)b * SEQ * D2 + dtile * 128;
    float acc[4][4];
    #pragma unroll
    for (int i = 0; i < 4; i++)
        #pragma unroll
        for (int j = 0; j < 4; j++) acc[i][j] = 0.f;

    int apr = t >> 3, apc = (t & 7) * 4;
    float4 pa = make_float4(0.f, 0.f, 0.f, 0.f);
    float4 pe[4];
    if (apr < RR) pa = *(const float4*)(Ab + (size_t)apr * SEQ + apc);
    #pragma unroll
    for (int li = 0; li < 4; li++) {
        int idx = t + li * 256;
        pe[li] = *(const float4*)(Eb + (size_t)(idx >> 5) * D2 + (idx & 31) * 4);
    }

    for (int n0 = 0; n0 < SEQ; n0 += 32) {
        Ash[apc + 0][apr] = pa.x; Ash[apc + 1][apr] = pa.y;
        Ash[apc + 2][apr] = pa.z; Ash[apc + 3][apr] = pa.w;
        #pragma unroll
        for (int li = 0; li < 4; li++) {
            int idx = t + li * 256;
            *(float4*)(&Es[idx >> 5][(idx & 31) * 4]) = pe[li];
        }
        __syncthreads();
        if (n0 + 32 < SEQ) {
            if (apr < RR) pa = *(const float4*)(Ab + (size_t)apr * SEQ + n0 + 32 + apc);
            #pragma unroll
            for (int li = 0; li < 4; li++) {
                int idx = t + li * 256;
                pe[li] = *(const float4*)(Eb + (size_t)(n0 + 32 + (idx >> 5)) * D2 + (idx & 31) * 4);
            }
        }
        #pragma unroll
        for (int n = 0; n < 32; n++) {
            float a[4], e[4];
            *(float4*)a = *(const float4*)(&Ash[n][ty * 4]);
            *(float4*)e = *(const float4*)(&Es[n][tx * 4]);
            #pragma unroll
            for (int i = 0; i < 4; i++)
                #pragma unroll
                for (int j = 0; j < 4; j++) acc[i][j] += a[i] * e[j];
        }
        __syncthreads();
    }
    #pragma unroll
    for (int i = 0; i < 4; i++) {
        int r = ty * 4 + i;
        if (r >= RR) continue;
        int d0 = dtile * 128 + tx * 4;
        uint32_t h0, h1, h2, h3, l0, l1, l2, l3;
        split_bf(acc[i][0], h0, l0); split_bf(acc[i][1], h1, l1);
        split_bf(acc[i][2], h2, l2); split_bf(acc[i][3], h3, l3);
        size_t o = (size_t)b * KMLP + (size_t)r * D3 + d0;
        *(uint2*)(g_BMh + o) = pack2(h0, h1, h2, h3);
        *(uint2*)(g_BMl + o) = pack2(l0, l1, l2, l3);
    }
}

// ======================================================================
// K5b: fill cat part of BM (exact: softmax rows sum to 1)
// ======================================================================
__global__ void k5b_cat(const float* __restrict__ cat) {
    int idx = (blockIdx.x * 256 + threadIdx.x) * 4;   // < 64*30*512
    int b = idx / (RR * DCAT);
    int rem = idx - b * RR * DCAT;
    int r = rem >> 9, d = rem & 511;
    float4 v = *(const float4*)(cat + (size_t)b * DCAT + d);
    uint32_t h0, h1, h2, h3, l0, l1, l2, l3;
    split_bf(v.x, h0, l0); split_bf(v.y, h1, l1);
    split_bf(v.z, h2, l2); split_bf(v.w, h3, l3);
    size_t o = (size_t)b * KMLP + (size_t)r * D3 + D2 + d;
    *(uint2*)(g_BMh + o) = pack2(h0, h1, h2, h3);
    *(uint2*)(g_BMl + o) = pack2(l0, l1, l2, l3);
}

// ======================================================================
// K6: split-bf16 mma.sync split-K GEMM, double-buffered pipeline.
//     tile 128(j) x 64(b), grid (16 jtiles, 9 ksplits), K chunks of 64.
// ======================================================================
#define K6_STG 49152
#define K6_WH  0
#define K6_WL  16384
#define K6_BH  32768
#define K6_BL  40960
#define K6_SMEM 98304

__global__ void __launch_bounds__(256, 1) k6_mlp(const float* __restrict__ Wm) {
    extern __shared__ __align__(128) char sm[];
    uint32_t sb = smem_u32(sm);
    int t = threadIdx.x;
    int lane = t & 31, wid = t >> 5;
    int j0 = blockIdx.x * 128;
    int ks = blockIdx.y;
    int kbeg = ks * KCHUNK;
    int wj = (wid >> 2) * 64;
    int wb = (wid & 3) * 16;

    float c[4][2][4];
    #pragma unroll
    for (int i = 0; i < 4; i++)
        #pragma unroll
        for (int j = 0; j < 2; j++)
            #pragma unroll
            for (int q = 0; q < 4; q++) c[i][j][q] = 0.f;

    float4 wreg[8];
    // prologue
    #pragma unroll
    for (int i = 0; i < 2; i++) {
        int idx = t + i * 256;
        int row = idx >> 3, seg = idx & 7;
        uint32_t doff = (uint32_t)(row * 128 + ((seg * 16) ^ ((row & 7) << 4)));
        cpasync16(sb + K6_BH + doff, g_BMh + (size_t)row * KMLP + kbeg + seg * 8);
        cpasync16(sb + K6_BL + doff, g_BMl + (size_t)row * KMLP + kbeg + seg * 8);
    }
    cpcommit();
    #pragma unroll
    for (int li = 0; li < 8; li++) {
        int idx = t + li * 256;
        wreg[li] = *(const float4*)(Wm + (size_t)(j0 + (idx >> 4)) * KMLP + kbeg + (idx & 15) * 4);
    }
    #pragma unroll
    for (int li = 0; li < 8; li++) {
        int idx = t + li * 256;
        int row = idx >> 4, seg = idx & 15;
        uint32_t h0, h1, h2, h3, l0, l1, l2, l3;
        split_bf(wreg[li].x, h0, l0); split_bf(wreg[li].y, h1, l1);
        split_bf(wreg[li].z, h2, l2); split_bf(wreg[li].w, h3, l3);
        uint32_t byte = (uint32_t)(row * 128 + ((seg * 8) ^ ((row & 7) << 4)));
        *(uint2*)(sm + K6_WH + byte) = pack2(h0, h1, h2, h3);
        *(uint2*)(sm + K6_WL + byte) = pack2(l0, l1, l2, l3);
    }

    int arow_l = lane & 15;
    int acol_l = (lane >> 4) * 16;
    int brow_l = (lane & 7) + ((lane >> 4) << 3);
    int bcol_l = ((lane >> 3) & 1) * 16;

    for (int cch = 0; cch < NCH6; cch++) {
        int s = cch & 1;
        uint32_t stg = (uint32_t)(s * K6_STG);
        cpwait0();
        __syncthreads();
        if (cch < NCH6 - 1) {
            uint32_t stg1 = (uint32_t)((s ^ 1) * K6_STG);
            int k0n = kbeg + (cch + 1) * 64;
            #pragma unroll
            for (int i = 0; i < 2; i++) {
                int idx = t + i * 256;
                int row = idx >> 3, seg = idx & 7;
                uint32_t doff = (uint32_t)(row * 128 + ((seg * 16) ^ ((row & 7) << 4)));
                cpasync16(sb + stg1 + K6_BH + doff, g_BMh + (size_t)row * KMLP + k0n + seg * 8);
                cpasync16(sb + stg1 + K6_BL + doff, g_BMl + (size_t)row * KMLP + k0n + seg * 8);
            }
            cpcommit();
            #pragma unroll
            for (int li = 0; li < 8; li++) {
                int idx = t + li * 256;
                wreg[li] = *(const float4*)(Wm + (size_t)(j0 + (idx >> 4)) * KMLP + k0n + (idx & 15) * 4);
            }
        }
        // MMA on stage s
        #pragma unroll
        for (int ksp = 0; ksp < 4; ksp++) {
            int kb = ksp * 32;
            uint32_t ah[4][4], al[4][4], bh[4], bl[4];
            #pragma unroll
            for (int mi = 0; mi < 4; mi++) {
                int row = wj + mi * 16 + arow_l;
                uint32_t off = (uint32_t)(row * 128 + ((kb + acol_l) ^ ((row & 7) << 4)));
                ldsm4(ah[mi], sb + stg + K6_WH + off);
                ldsm4(al[mi], sb + stg + K6_WL + off);
            }
            {
                int row = wb + brow_l;
                uint32_t off = (uint32_t)(row * 128 + ((kb + bcol_l) ^ ((row & 7) << 4)));
                ldsm4(bh, sb + stg + K6_BH + off);
                ldsm4(bl, sb + stg + K6_BL + off);
            }
            #pragma unroll
            for (int mi = 0; mi < 4; mi++)
                #pragma unroll
                for (int j = 0; j < 2; j++) {
                    mma16816(c[mi][j], ah[mi], &bh[j * 2]);
                    mma16816(c[mi][j], ah[mi], &bl[j * 2]);
                    mma16816(c[mi][j], al[mi], &bh[j * 2]);
                }
        }
        if (cch < NCH6 - 1) {
            uint32_t stg1 = (uint32_t)((s ^ 1) * K6_STG);
            #pragma unroll
            for (int li = 0; li < 8; li++) {
                int idx = t + li * 256;
                int row = idx >> 4, seg = idx & 15;
                uint32_t h0, h1, h2, h3, l0, l1, l2, l3;
                split_bf(wreg[li].x, h0, l0); split_bf(wreg[li].y, h1, l1);
                split_bf(wreg[li].z, h2, l2); split_bf(wreg[li].w, h3, l3);
                uint32_t byte = (uint32_t)(row * 128 + ((seg * 8) ^ ((row & 7) << 4)));
                *(uint2*)(sm + stg1 + K6_WH + byte) = pack2(h0, h1, h2, h3);
                *(uint2*)(sm + stg1 + K6_WL + byte) = pack2(l0, l1, l2, l3);
            }
        }
    }

    #pragma unroll
    for (int mi = 0; mi < 4; mi++) {
        int jr = j0 + wj + mi * 16 + (lane >> 2);
        #pragma unroll
        for (int j = 0; j < 2; j++) {
            int bc = wb + j * 8 + (lane & 3) * 2;
            float* d0 = g_part + ((size_t)ks * MLPD + jr) * BATCH + bc;
            float* d1 = g_part + ((size_t)ks * MLPD + jr + 8) * BATCH + bc;
            d0[0] = c[mi][j][0]; d0[1] = c[mi][j][1];
            d1[0] = c[mi][j][2]; d1[1] = c[mi][j][3];
        }
    }
}

// ======================================================================
// K7: reduce split-K + bias -> d_out
// ======================================================================
__global__ void k7_reduce(const float* __restrict__ bias, float* __restrict__ out) {
    int idx = blockIdx.x * 256 + threadIdx.x;
    int j = idx >> 6, b = idx & 63;
    float s = bias[j];
    #pragma unroll
    for (int ks = 0; ks < KSPLIT; ks++)
        s += g_part[((size_t)ks * MLPD + j) * BATCH + b];
    out[(size_t)b * MLPD + j] = s;
}

// ======================================================================
extern "C" void kernel_launch(void* const* d_in, const int* in_sizes, int n_in,
                              void* d_out, int out_size) {
    const float* enc = nullptr;
    const int*   len = nullptr;
    const float* cat = nullptr;
    const float* W1 = nullptr;
    const float* W2 = nullptr;
    const float* Wm = nullptr;
    const float* bm = nullptr;
    for (int i = 0; i < n_in; i++) {
        switch (in_sizes[i]) {
            case 67108864: enc = (const float*)d_in[i]; break;
            case 64:       len = (const int*)d_in[i];   break;
            case 32768:    cat = (const float*)d_in[i]; break;
            case 537600:   W1  = (const float*)d_in[i]; break;
            case 10500:    W2  = (const float*)d_in[i]; break;
            case 94371840: Wm  = (const float*)d_in[i]; break;
            case 2048:     bm  = (const float*)d_in[i]; break;
            default: break;
        }
    }
    float* outf = (float*)d_out;
    float* outO = outf;
    float* outA = outf + BATCH * MLPD;

    cudaFuncSetAttribute(k1_s1s2, cudaFuncAttributeMaxDynamicSharedMemorySize, K1_SMEM);
    cudaFuncSetAttribute(k6_mlp, cudaFuncAttributeMaxDynamicSharedMemorySize, K6_SMEM);

    k0_catc   <<<BATCH, 256>>>(W1, cat);
    k0b_w1    <<<(NW1 * D2) / 256, 256>>>(W1);
    k1_s1s2   <<<ROWS / 64, 256, K1_SMEM>>>(enc, W2);
    k3_softmax<<<BATCH * RR, 256>>>(len, outA);
    k4_mgemm  <<<dim3(8, BATCH), 256>>>(enc, outA);
    k5b_cat   <<<(BATCH * RR * DCAT) / 1024, 256>>>(cat);
    k6_mlp    <<<dim3(MLPD / 128, KSPLIT), 256, K6_SMEM>>>(Wm);
    k7_reduce <<<(BATCH * MLPD) / 256, 256>>>(bm, outO);
}

// round 7
// speedup vs baseline: 3.0859x; 1.3560x over previous
#include <cuda_runtime.h>
#include <cuda_fp16.h>
#include <math.h>
#include <stdint.h>

#define BATCH 64
#define SEQ   1024
#define D2    1024
#define DCAT  512
#define D3    1536
#define DA    350
#define DA_PAD 352
#define NW1   384
#define RR    30
#define MLPD  2048
#define KMLP  46080
#define ROWS  65536
#define NEGV  (-1e9f)
#define KSPLIT 18
#define KCHUNK 2560            // KMLP / 18
#define NCH6   40              // KCHUNK / 64

// ---------------- scratch ----------------
__device__ float g_catc[BATCH * DA_PAD];
__device__ float g_s2[BATCH * RR * SEQ];
__device__ float g_part[KSPLIT * MLPD * BATCH];
__device__ __align__(128) __half g_W1H[NW1 * D2];
__device__ __align__(128) __half g_BM[BATCH * KMLP];

// ---------------- helpers ----------------
__device__ __forceinline__ uint32_t smem_u32(const void* p) {
    uint32_t r;
    asm("{ .reg .u64 t; cvta.to.shared.u64 t, %1; cvt.u32.u64 %0, t; }" : "=r"(r) : "l"(p));
    return r;
}
__device__ __forceinline__ void ldsm4(uint32_t* r, uint32_t addr) {
    asm volatile("ldmatrix.sync.aligned.m8n8.x4.shared.b16 {%0,%1,%2,%3}, [%4];"
                 : "=r"(r[0]), "=r"(r[1]), "=r"(r[2]), "=r"(r[3]) : "r"(addr));
}
__device__ __forceinline__ void mma16816(float* c, const uint32_t* a, const uint32_t* b) {
    asm volatile(
        "mma.sync.aligned.m16n8k16.row.col.f32.f16.f16.f32 "
        "{%0,%1,%2,%3}, {%4,%5,%6,%7}, {%8,%9}, {%0,%1,%2,%3};"
        : "+f"(c[0]), "+f"(c[1]), "+f"(c[2]), "+f"(c[3])
        : "r"(a[0]), "r"(a[1]), "r"(a[2]), "r"(a[3]), "r"(b[0]), "r"(b[1]));
}
__device__ __forceinline__ void cpasync16(uint32_t dst, const void* src) {
    asm volatile("cp.async.cg.shared.global [%0], [%1], 16;" :: "r"(dst), "l"(src));
}
__device__ __forceinline__ void cpcommit() { asm volatile("cp.async.commit_group;"); }
__device__ __forceinline__ void cpwait0()  { asm volatile("cp.async.wait_group 0;"); }

__device__ __forceinline__ uint32_t f2h2(float a, float b) {
    return (uint32_t)__half_as_ushort(__float2half_rn(a)) |
           ((uint32_t)__half_as_ushort(__float2half_rn(b)) << 16);
}
__device__ __forceinline__ uint2 cvt4h(float4 v) {
    return make_uint2(f2h2(v.x, v.y), f2h2(v.z, v.w));
}

// ======================================================================
// K0: catc[b,a] = W1_cat[a,:] . cat_emb[b,:]
// ======================================================================
__global__ void k0_catc(const float* __restrict__ W1, const float* __restrict__ cat) {
    int b = blockIdx.x;
    int warp = threadIdx.x >> 5, lane = threadIdx.x & 31;
    const float* cb = cat + b * DCAT;
    for (int a = warp; a < DA; a += 8) {
        const float* w = W1 + (size_t)a * D3 + D2;
        float s = 0.f;
        for (int d = lane; d < DCAT; d += 32) s += w[d] * cb[d];
        #pragma unroll
        for (int o = 16; o; o >>= 1) s += __shfl_xor_sync(0xffffffffu, s, o);
        if (lane == 0) g_catc[b * DA_PAD + a] = s;
    }
}

// ======================================================================
// K0b: W1 enc-part -> fp16, [384][1024], rows >= 350 zeroed
// ======================================================================
__global__ void k0b_w1(const float* __restrict__ W1) {
    int i = blockIdx.x * 256 + threadIdx.x;
    int row = i >> 10, k = i & 1023;
    float v = (row < DA) ? W1[(size_t)row * D3 + k] : 0.f;
    g_W1H[i] = __float2half_rn(v);
}

// ======================================================================
// K1: fp16 mma.sync GEMM, tile 64(M) x 384(N), K chunks of 32,
//     double-buffered, fused s2 epilogue. grid 1024, 256 thr.
// ======================================================================
#define K1_STG   28672
#define K1_A     0
#define K1_B     4096
#define K1_SMEM  57344
#define SSTR     200

__global__ void __launch_bounds__(256, 1) k1_s1s2(
    const float* __restrict__ enc,
    const float* __restrict__ W2)
{
    extern __shared__ __align__(128) char sm[];
    uint32_t sb = smem_u32(sm);
    int t = threadIdx.x;
    int lane = t & 31, wid = t >> 5;
    int m0 = blockIdx.x * 64;
    int b = m0 >> 10;
    int wm = (wid >> 2) * 32;
    int wn = (wid & 3) * 96;

    float c[2][12][4];
    #pragma unroll
    for (int i = 0; i < 2; i++)
        #pragma unroll
        for (int j = 0; j < 12; j++)
            #pragma unroll
            for (int q = 0; q < 4; q++) c[i][j][q] = 0.f;

    int ar = t >> 2, ac = t & 3;
    const float* aptr = enc + (size_t)(m0 + ar) * D2 + ac * 8;
    uint32_t a_sts = (uint32_t)(ar * 64 + ((ac ^ ((ar >> 1) & 3)) << 4));

    float4 pa0, pa1;
    // prologue: B chunk0 via cp.async, A chunk0 via regs
    #pragma unroll
    for (int i = 0; i < 6; i++) {
        int idx = t + i * 256;
        int n = idx >> 2, ch = idx & 3;
        uint32_t doff = (uint32_t)(n * 64 + ((ch ^ ((n >> 1) & 3)) << 4));
        cpasync16(sb + K1_B + doff, g_W1H + (size_t)n * D2 + ch * 8);
    }
    cpcommit();
    pa0 = *(const float4*)(aptr);
    pa1 = *(const float4*)(aptr + 4);
    *(uint4*)(sm + K1_A + a_sts) =
        make_uint4(f2h2(pa0.x, pa0.y), f2h2(pa0.z, pa0.w), f2h2(pa1.x, pa1.y), f2h2(pa1.z, pa1.w));

    for (int cch = 0; cch < 32; cch++) {
        int s = cch & 1;
        uint32_t stg = (uint32_t)(s * K1_STG);
        cpwait0();
        __syncthreads();
        if (cch < 31) {
            uint32_t stg1 = (uint32_t)((s ^ 1) * K1_STG);
            int k0n = (cch + 1) * 32;
            #pragma unroll
            for (int i = 0; i < 6; i++) {
                int idx = t + i * 256;
                int n = idx >> 2, ch = idx & 3;
                uint32_t doff = (uint32_t)(n * 64 + ((ch ^ ((n >> 1) & 3)) << 4));
                cpasync16(sb + stg1 + K1_B + doff, g_W1H + (size_t)n * D2 + k0n + ch * 8);
            }
            cpcommit();
            pa0 = *(const float4*)(aptr + k0n);
            pa1 = *(const float4*)(aptr + k0n + 4);
        }
        // MMA on stage s
        #pragma unroll
        for (int kstep = 0; kstep < 2; kstep++) {
            uint32_t ah[2][4];
            #pragma unroll
            for (int mi = 0; mi < 2; mi++) {
                int r = wm + mi * 16 + (lane & 15);
                int ch = kstep * 2 + (lane >> 4);
                uint32_t off = (uint32_t)(r * 64 + ((ch ^ ((r >> 1) & 3)) << 4));
                ldsm4(ah[mi], sb + stg + K1_A + off);
            }
            #pragma unroll
            for (int q = 0; q < 6; q++) {
                uint32_t bh[4];
                int n = wn + q * 16 + (lane & 7) + ((lane >> 4) << 3);
                int ch = kstep * 2 + ((lane >> 3) & 1);
                uint32_t off = (uint32_t)(n * 64 + ((ch ^ ((n >> 1) & 3)) << 4));
                ldsm4(bh, sb + stg + K1_B + off);
                #pragma unroll
                for (int mi = 0; mi < 2; mi++)
                    #pragma unroll
                    for (int j = 0; j < 2; j++)
                        mma16816(c[mi][q * 2 + j], ah[mi], &bh[j * 2]);
            }
        }
        if (cch < 31) {
            uint32_t stg1 = (uint32_t)((s ^ 1) * K1_STG);
            *(uint4*)(sm + stg1 + K1_A + a_sts) =
                make_uint4(f2h2(pa0.x, pa0.y), f2h2(pa0.z, pa0.w), f2h2(pa1.x, pa1.y), f2h2(pa1.z, pa1.w));
        }
    }

    // ---- fused epilogue: s2 = tanh(c + catc) @ W2^T ----
    // smem reuse: W2f [192*32] f32 @0 (24576) | catcs f32 @24576 (1536) | S half [64][SSTR] @26112
    __syncthreads();
    float* W2f  = (float*)(sm);
    float* catcs = (float*)(sm + 24576);
    __half* S   = (__half*)(sm + 26112);
    for (int i = t; i < 384; i += 256)
        catcs[i] = (i < DA) ? g_catc[b * DA_PAD + i] : 0.f;

    float s2acc[8];
    #pragma unroll
    for (int rr = 0; rr < 8; rr++) s2acc[rr] = 0.f;
    int ml = t >> 2, rcol = t & 3;

    #pragma unroll
    for (int p = 0; p < 2; p++) {
        __syncthreads();
        for (int idx = t; idx < 192 * 32; idx += 256) {
            int n = idx >> 5, r = idx & 31;
            int ng = p * 192 + n;
            W2f[idx] = (r < RR && ng < DA) ? W2[r * DA + ng] : 0.f;
        }
        if (((wid & 3) >> 1) == p) {
            #pragma unroll
            for (int mi = 0; mi < 2; mi++) {
                int lr = wm + mi * 16 + (lane >> 2);
                #pragma unroll
                for (int cj = 0; cj < 12; cj++) {
                    int ng = wn + cj * 8 + (lane & 3) * 2;
                    int nl = ng - p * 192;
                    float cc0 = catcs[ng], cc1 = catcs[ng + 1];
                    *(uint32_t*)&S[lr * SSTR + nl] =
                        f2h2(tanhf(c[mi][cj][0] + cc0), tanhf(c[mi][cj][1] + cc1));
                    *(uint32_t*)&S[(lr + 8) * SSTR + nl] =
                        f2h2(tanhf(c[mi][cj][2] + cc0), tanhf(c[mi][cj][3] + cc1));
                }
            }
        }
        __syncthreads();
        const __half* Sp = S + ml * SSTR;
        const float* Wp = W2f + rcol * 8;
        #pragma unroll 4
        for (int n = 0; n < 192; n++) {
            float a = __half2float(Sp[n]);
            float4 w0 = *(const float4*)(Wp + n * 32);
            float4 w1 = *(const float4*)(Wp + n * 32 + 4);
            s2acc[0] += a * w0.x; s2acc[1] += a * w0.y;
            s2acc[2] += a * w0.z; s2acc[3] += a * w0.w;
            s2acc[4] += a * w1.x; s2acc[5] += a * w1.y;
            s2acc[6] += a * w1.z; s2acc[7] += a * w1.w;
        }
    }
    int npos = (m0 + ml) & 1023;
    #pragma unroll
    for (int rr = 0; rr < 8; rr++) {
        int r = rcol * 8 + rr;
        if (r < RR) g_s2[((size_t)b * RR + r) * SEQ + npos] = s2acc[rr];
    }
}

// ======================================================================
// K3: masked softmax; writes A into d_out
// ======================================================================
__global__ void k3_softmax(const int* __restrict__ len, float* __restrict__ outA) {
    __shared__ float sred[8];
    int br = blockIdx.x;
    int b = br / RR;
    int t = threadIdx.x;
    int lane = t & 31, warp = t >> 5;
    const float* src = g_s2 + (size_t)br * SEQ;
    int L = len[b];

    float4 v = *(const float4*)(src + t * 4);
    float vv[4] = {v.x, v.y, v.z, v.w};
    #pragma unroll
    for (int j = 0; j < 4; j++) if (t * 4 + j >= L) vv[j] = NEGV;

    float mx = fmaxf(fmaxf(vv[0], vv[1]), fmaxf(vv[2], vv[3]));
    #pragma unroll
    for (int o = 16; o; o >>= 1) mx = fmaxf(mx, __shfl_xor_sync(0xffffffffu, mx, o));
    if (lane == 0) sred[warp] = mx;
    __syncthreads();
    mx = sred[0];
    #pragma unroll
    for (int w = 1; w < 8; w++) mx = fmaxf(mx, sred[w]);

    float e[4], s = 0.f;
    #pragma unroll
    for (int j = 0; j < 4; j++) { e[j] = __expf(vv[j] - mx); s += e[j]; }
    #pragma unroll
    for (int o = 16; o; o >>= 1) s += __shfl_xor_sync(0xffffffffu, s, o);
    __syncthreads();
    if (lane == 0) sred[warp] = s;
    __syncthreads();
    s = 0.f;
    #pragma unroll
    for (int w = 0; w < 8; w++) s += sred[w];
    float inv = 1.f / s;

    *(float4*)(outA + (size_t)br * SEQ + t * 4) =
        make_float4(e[0] * inv, e[1] * inv, e[2] * inv, e[3] * inv);
}

// ======================================================================
// K4: M_enc = A @ enc (fp32 SIMT, reg-prefetched); writes BM fp16
// ======================================================================
__global__ void k4_mgemm(const float* __restrict__ enc, const float* __restrict__ outA) {
    __shared__ float Ash[32][32];
    __shared__ float Es[32][128];
    int t = threadIdx.x;
    int dtile = blockIdx.x, b = blockIdx.y;
    int ty = t >> 5, tx = t & 31;
    const float* Ab = outA + (size_t)b * RR * SEQ;
    const float* Eb = enc + (size_t)b * SEQ * D2 + dtile * 128;
    float acc[4][4];
    #pragma unroll
    for (int i = 0; i < 4; i++)
        #pragma unroll
        for (int j = 0; j < 4; j++) acc[i][j] = 0.f;

    int apr = t >> 3, apc = (t & 7) * 4;
    float4 pa = make_float4(0.f, 0.f, 0.f, 0.f);
    float4 pe[4];
    if (apr < RR) pa = *(const float4*)(Ab + (size_t)apr * SEQ + apc);
    #pragma unroll
    for (int li = 0; li < 4; li++) {
        int idx = t + li * 256;
        pe[li] = *(const float4*)(Eb + (size_t)(idx >> 5) * D2 + (idx & 31) * 4);
    }

    for (int n0 = 0; n0 < SEQ; n0 += 32) {
        Ash[apc + 0][apr] = pa.x; Ash[apc + 1][apr] = pa.y;
        Ash[apc + 2][apr] = pa.z; Ash[apc + 3][apr] = pa.w;
        #pragma unroll
        for (int li = 0; li < 4; li++) {
            int idx = t + li * 256;
            *(float4*)(&Es[idx >> 5][(idx & 31) * 4]) = pe[li];
        }
        __syncthreads();
        if (n0 + 32 < SEQ) {
            if (apr < RR) pa = *(const float4*)(Ab + (size_t)apr * SEQ + n0 + 32 + apc);
            #pragma unroll
            for (int li = 0; li < 4; li++) {
                int idx = t + li * 256;
                pe[li] = *(const float4*)(Eb + (size_t)(n0 + 32 + (idx >> 5)) * D2 + (idx & 31) * 4);
            }
        }
        #pragma unroll
        for (int n = 0; n < 32; n++) {
            float a[4], e[4];
            *(float4*)a = *(const float4*)(&Ash[n][ty * 4]);
            *(float4*)e = *(const float4*)(&Es[n][tx * 4]);
            #pragma unroll
            for (int i = 0; i < 4; i++)
                #pragma unroll
                for (int j = 0; j < 4; j++) acc[i][j] += a[i] * e[j];
        }
        __syncthreads();
    }
    #pragma unroll
    for (int i = 0; i < 4; i++) {
        int r = ty * 4 + i;
        if (r >= RR) continue;
        int d0 = dtile * 128 + tx * 4;
        size_t o = (size_t)b * KMLP + (size_t)r * D3 + d0;
        *(uint2*)(g_BM + o) = cvt4h(make_float4(acc[i][0], acc[i][1], acc[i][2], acc[i][3]));
    }
}

// ======================================================================
// K5b: fill cat part of BM (exact: softmax rows sum to 1)
// ======================================================================
__global__ void k5b_cat(const float* __restrict__ cat) {
    int idx = (blockIdx.x * 256 + threadIdx.x) * 4;
    int b = idx / (RR * DCAT);
    int rem = idx - b * RR * DCAT;
    int r = rem >> 9, d = rem & 511;
    float4 v = *(const float4*)(cat + (size_t)b * DCAT + d);
    size_t o = (size_t)b * KMLP + (size_t)r * D3 + D2 + d;
    *(uint2*)(g_BM + o) = cvt4h(v);
}

// ======================================================================
// K6: fp16 mma.sync split-K GEMM, double-buffered.
//     tile 128(j) x 64(b), grid (16 jtiles, 18 ksplits), K chunks of 64.
// ======================================================================
#define K6_STG 24576
#define K6_W   0
#define K6_B   16384
#define K6_SMEM 49152

__global__ void __launch_bounds__(256, 1) k6_mlp(const float* __restrict__ Wm) {
    extern __shared__ __align__(128) char sm[];
    uint32_t sb = smem_u32(sm);
    int t = threadIdx.x;
    int lane = t & 31, wid = t >> 5;
    int j0 = blockIdx.x * 128;
    int ks = blockIdx.y;
    int kbeg = ks * KCHUNK;
    int wj = (wid >> 2) * 64;
    int wb = (wid & 3) * 16;

    float c[4][2][4];
    #pragma unroll
    for (int i = 0; i < 4; i++)
        #pragma unroll
        for (int j = 0; j < 2; j++)
            #pragma unroll
            for (int q = 0; q < 4; q++) c[i][j][q] = 0.f;

    float4 wreg[8];
    // prologue
    #pragma unroll
    for (int i = 0; i < 2; i++) {
        int idx = t + i * 256;
        int row = idx >> 3, seg = idx & 7;
        uint32_t doff = (uint32_t)(row * 128 + ((seg * 16) ^ ((row & 7) << 4)));
        cpasync16(sb + K6_B + doff, g_BM + (size_t)row * KMLP + kbeg + seg * 8);
    }
    cpcommit();
    #pragma unroll
    for (int li = 0; li < 8; li++) {
        int idx = t + li * 256;
        wreg[li] = *(const float4*)(Wm + (size_t)(j0 + (idx >> 4)) * KMLP + kbeg + (idx & 15) * 4);
    }
    #pragma unroll
    for (int li = 0; li < 8; li++) {
        int idx = t + li * 256;
        int row = idx >> 4, seg = idx & 15;
        uint32_t byte = (uint32_t)(row * 128 + ((seg * 8) ^ ((row & 7) << 4)));
        *(uint2*)(sm + K6_W + byte) = cvt4h(wreg[li]);
    }

    int arow_l = lane & 15;
    int acol_l = (lane >> 4) * 16;
    int brow_l = (lane & 7) + ((lane >> 4) << 3);
    int bcol_l = ((lane >> 3) & 1) * 16;

    for (int cch = 0; cch < NCH6; cch++) {
        int s = cch & 1;
        uint32_t stg = (uint32_t)(s * K6_STG);
        cpwait0();
        __syncthreads();
        if (cch < NCH6 - 1) {
            uint32_t stg1 = (uint32_t)((s ^ 1) * K6_STG);
            int k0n = kbeg + (cch + 1) * 64;
            #pragma unroll
            for (int i = 0; i < 2; i++) {
                int idx = t + i * 256;
                int row = idx >> 3, seg = idx & 7;
                uint32_t doff = (uint32_t)(row * 128 + ((seg * 16) ^ ((row & 7) << 4)));
                cpasync16(sb + stg1 + K6_B + doff, g_BM + (size_t)row * KMLP + k0n + seg * 8);
            }
            cpcommit();
            #pragma unroll
            for (int li = 0; li < 8; li++) {
                int idx = t + li * 256;
                wreg[li] = *(const float4*)(Wm + (size_t)(j0 + (idx >> 4)) * KMLP + k0n + (idx & 15) * 4);
            }
        }
        #pragma unroll
        for (int ksp = 0; ksp < 4; ksp++) {
            int kb = ksp * 32;
            uint32_t ah[4][4], bh[4];
            #pragma unroll
            for (int mi = 0; mi < 4; mi++) {
                int row = wj + mi * 16 + arow_l;
                uint32_t off = (uint32_t)(row * 128 + ((kb + acol_l) ^ ((row & 7) << 4)));
                ldsm4(ah[mi], sb + stg + K6_W + off);
            }
            {
                int row = wb + brow_l;
                uint32_t off = (uint32_t)(row * 128 + ((kb + bcol_l) ^ ((row & 7) << 4)));
                ldsm4(bh, sb + stg + K6_B + off);
            }
            #pragma unroll
            for (int mi = 0; mi < 4; mi++)
                #pragma unroll
                for (int j = 0; j < 2; j++)
                    mma16816(c[mi][j], ah[mi], &bh[j * 2]);
        }
        if (cch < NCH6 - 1) {
            uint32_t stg1 = (uint32_t)((s ^ 1) * K6_STG);
            #pragma unroll
            for (int li = 0; li < 8; li++) {
                int idx = t + li * 256;
                int row = idx >> 4, seg = idx & 15;
                uint32_t byte = (uint32_t)(row * 128 + ((seg * 8) ^ ((row & 7) << 4)));
                *(uint2*)(sm + stg1 + K6_W + byte) = cvt4h(wreg[li]);
            }
        }
    }

    #pragma unroll
    for (int mi = 0; mi < 4; mi++) {
        int jr = j0 + wj + mi * 16 + (lane >> 2);
        #pragma unroll
        for (int j = 0; j < 2; j++) {
            int bc = wb + j * 8 + (lane & 3) * 2;
            float* d0 = g_part + ((size_t)ks * MLPD + jr) * BATCH + bc;
            float* d1 = g_part + ((size_t)ks * MLPD + jr + 8) * BATCH + bc;
            d0[0] = c[mi][j][0]; d0[1] = c[mi][j][1];
            d1[0] = c[mi][j][2]; d1[1] = c[mi][j][3];
        }
    }
}

// ======================================================================
// K7: reduce split-K + bias -> d_out
// ======================================================================
__global__ void k7_reduce(const float* __restrict__ bias, float* __restrict__ out) {
    int idx = blockIdx.x * 256 + threadIdx.x;
    int j = idx >> 6, b = idx & 63;
    float s = bias[j];
    #pragma unroll
    for (int ks = 0; ks < KSPLIT; ks++)
        s += g_part[((size_t)ks * MLPD + j) * BATCH + b];
    out[(size_t)b * MLPD + j] = s;
}

// ======================================================================
extern "C" void kernel_launch(void* const* d_in, const int* in_sizes, int n_in,
                              void* d_out, int out_size) {
    const float* enc = nullptr;
    const int*   len = nullptr;
    const float* cat = nullptr;
    const float* W1 = nullptr;
    const float* W2 = nullptr;
    const float* Wm = nullptr;
    const float* bm = nullptr;
    for (int i = 0; i < n_in; i++) {
        switch (in_sizes[i]) {
            case 67108864: enc = (const float*)d_in[i]; break;
            case 64:       len = (const int*)d_in[i];   break;
            case 32768:    cat = (const float*)d_in[i]; break;
            case 537600:   W1  = (const float*)d_in[i]; break;
            case 10500:    W2  = (const float*)d_in[i]; break;
            case 94371840: Wm  = (const float*)d_in[i]; break;
            case 2048:     bm  = (const float*)d_in[i]; break;
            default: break;
        }
    }
    float* outf = (float*)d_out;
    float* outO = outf;
    float* outA = outf + BATCH * MLPD;

    cudaFuncSetAttribute(k1_s1s2, cudaFuncAttributeMaxDynamicSharedMemorySize, K1_SMEM);
    cudaFuncSetAttribute(k6_mlp, cudaFuncAttributeMaxDynamicSharedMemorySize, K6_SMEM);

    k0_catc   <<<BATCH, 256>>>(W1, cat);
    k0b_w1    <<<(NW1 * D2) / 256, 256>>>(W1);
    k1_s1s2   <<<ROWS / 64, 256, K1_SMEM>>>(enc, W2);
    k3_softmax<<<BATCH * RR, 256>>>(len, outA);
    k4_mgemm  <<<dim3(8, BATCH), 256>>>(enc, outA);
    k5b_cat   <<<(BATCH * RR * DCAT) / 1024, 256>>>(cat);
    k6_mlp    <<<dim3(MLPD / 128, KSPLIT), 256, K6_SMEM>>>(Wm);
    k7_reduce <<<(BATCH * MLPD) / 256, 256>>>(bm, outO);
}

// round 9
// speedup vs baseline: 4.3186x; 1.3995x over previous
#include <cuda_runtime.h>
#include <cuda_fp16.h>
#include <math.h>
#include <stdint.h>

#define BATCH 64
#define SEQ   1024
#define D2    1024
#define DCAT  512
#define D3    1536
#define DA    350
#define DA_PAD 352
#define NW1   384
#define RR    30
#define MLPD  2048
#define KMLP  46080
#define ROWS  65536
#define NEGV  (-1e9f)
#define KSPLIT 18
#define KCHUNK 2560
#define NCH6   40

// ---------------- scratch ----------------
__device__ float g_catc[BATCH * DA_PAD];
__device__ float g_s2[BATCH * RR * SEQ];
__device__ float g_part[KSPLIT * MLPD * BATCH];
__device__ __align__(128) __half g_W1H[NW1 * D2];
__device__ __align__(128) __half g_W2H[32 * 384];          // [r pad 32][n pad 384]
__device__ __align__(128) __half g_AH[BATCH * 32 * SEQ];   // probs fp16, rows 30,31 zero
__device__ __align__(128) __half g_BM[BATCH * KMLP];

// ---------------- helpers ----------------
__device__ __forceinline__ uint32_t smem_u32(const void* p) {
    uint32_t r;
    asm("{ .reg .u64 t; cvta.to.shared.u64 t, %1; cvt.u32.u64 %0, t; }" : "=r"(r) : "l"(p));
    return r;
}
__device__ __forceinline__ void ldsm4(uint32_t* r, uint32_t addr) {
    asm volatile("ldmatrix.sync.aligned.m8n8.x4.shared.b16 {%0,%1,%2,%3}, [%4];"
                 : "=r"(r[0]), "=r"(r[1]), "=r"(r[2]), "=r"(r[3]) : "r"(addr));
}
__device__ __forceinline__ void ldsm4t(uint32_t* r, uint32_t addr) {
    asm volatile("ldmatrix.sync.aligned.m8n8.x4.trans.shared.b16 {%0,%1,%2,%3}, [%4];"
                 : "=r"(r[0]), "=r"(r[1]), "=r"(r[2]), "=r"(r[3]) : "r"(addr));
}
__device__ __forceinline__ void mma16816(float* c, const uint32_t* a, const uint32_t* b) {
    asm volatile(
        "mma.sync.aligned.m16n8k16.row.col.f32.f16.f16.f32 "
        "{%0,%1,%2,%3}, {%4,%5,%6,%7}, {%8,%9}, {%0,%1,%2,%3};"
        : "+f"(c[0]), "+f"(c[1]), "+f"(c[2]), "+f"(c[3])
        : "r"(a[0]), "r"(a[1]), "r"(a[2]), "r"(a[3]), "r"(b[0]), "r"(b[1]));
}
__device__ __forceinline__ void cpasync16(uint32_t dst, const void* src) {
    asm volatile("cp.async.cg.shared.global [%0], [%1], 16;" :: "r"(dst), "l"(src));
}
__device__ __forceinline__ void cpcommit() { asm volatile("cp.async.commit_group;"); }
__device__ __forceinline__ void cpwait0()  { asm volatile("cp.async.wait_group 0;"); }

__device__ __forceinline__ uint32_t f2h2(float a, float b) {
    return (uint32_t)__half_as_ushort(__float2half_rn(a)) |
           ((uint32_t)__half_as_ushort(__float2half_rn(b)) << 16);
}
__device__ __forceinline__ uint2 cvt4h(float4 v) {
    return make_uint2(f2h2(v.x, v.y), f2h2(v.z, v.w));
}

// ======================================================================
// K0: catc[b,a] = W1_cat[a,:] . cat_emb[b,:]
// ======================================================================
__global__ void k0_catc(const float* __restrict__ W1, const float* __restrict__ cat) {
    int b = blockIdx.x;
    int warp = threadIdx.x >> 5, lane = threadIdx.x & 31;
    const float* cb = cat + b * DCAT;
    for (int a = warp; a < DA; a += 8) {
        const float* w = W1 + (size_t)a * D3 + D2;
        float s = 0.f;
        for (int d = lane; d < DCAT; d += 32) s += w[d] * cb[d];
        #pragma unroll
        for (int o = 16; o; o >>= 1) s += __shfl_xor_sync(0xffffffffu, s, o);
        if (lane == 0) g_catc[b * DA_PAD + a] = s;
    }
}

// ======================================================================
// K0b: W1 enc-part -> fp16 [384][1024]; K0b2: W2 -> fp16 [32][384]
// ======================================================================
__global__ void k0b_w1(const float* __restrict__ W1) {
    int i = blockIdx.x * 256 + threadIdx.x;
    int row = i >> 10, k = i & 1023;
    float v = (row < DA) ? W1[(size_t)row * D3 + k] : 0.f;
    g_W1H[i] = __float2half_rn(v);
}
__global__ void k0b2_w2(const float* __restrict__ W2) {
    int i = blockIdx.x * 256 + threadIdx.x;   // < 12288
    int r = i / 384, n = i - r * 384;
    float v = (r < RR && n < DA) ? W2[r * DA + n] : 0.f;
    g_W2H[i] = __float2half_rn(v);
}

// ======================================================================
// K1: fp16 mma.sync GEMM tile 64x384, double-buffered; tensor-core
//     fused s2 epilogue (S fp16 @smem, W2 fp16).
// ======================================================================
#define K1_STG   28672
#define K1_A     0
#define K1_B     4096
#define K1_SMEM  76288
#define EP_STRB  784                       // 392 halfs per row, bank-safe
#define EP_W2    50176                     // 64*784

__global__ void __launch_bounds__(256, 1) k1_s1s2(
    const float* __restrict__ enc)
{
    extern __shared__ __align__(128) char sm[];
    uint32_t sb = smem_u32(sm);
    int t = threadIdx.x;
    int lane = t & 31, wid = t >> 5;
    int m0 = blockIdx.x * 64;
    int b = m0 >> 10;
    int wm = (wid >> 2) * 32;
    int wn = (wid & 3) * 96;

    float c[2][12][4];
    #pragma unroll
    for (int i = 0; i < 2; i++)
        #pragma unroll
        for (int j = 0; j < 12; j++)
            #pragma unroll
            for (int q = 0; q < 4; q++) c[i][j][q] = 0.f;

    int ar = t >> 2, ac = t & 3;
    const float* aptr = enc + (size_t)(m0 + ar) * D2 + ac * 8;
    uint32_t a_sts = (uint32_t)(ar * 64 + ((ac ^ ((ar >> 1) & 3)) << 4));

    float4 pa0, pa1;
    #pragma unroll
    for (int i = 0; i < 6; i++) {
        int idx = t + i * 256;
        int n = idx >> 2, ch = idx & 3;
        uint32_t doff = (uint32_t)(n * 64 + ((ch ^ ((n >> 1) & 3)) << 4));
        cpasync16(sb + K1_B + doff, g_W1H + (size_t)n * D2 + ch * 8);
    }
    cpcommit();
    pa0 = *(const float4*)(aptr);
    pa1 = *(const float4*)(aptr + 4);
    *(uint4*)(sm + K1_A + a_sts) =
        make_uint4(f2h2(pa0.x, pa0.y), f2h2(pa0.z, pa0.w), f2h2(pa1.x, pa1.y), f2h2(pa1.z, pa1.w));

    for (int cch = 0; cch < 32; cch++) {
        int s = cch & 1;
        uint32_t stg = (uint32_t)(s * K1_STG);
        cpwait0();
        __syncthreads();
        if (cch < 31) {
            uint32_t stg1 = (uint32_t)((s ^ 1) * K1_STG);
            int k0n = (cch + 1) * 32;
            #pragma unroll
            for (int i = 0; i < 6; i++) {
                int idx = t + i * 256;
                int n = idx >> 2, ch = idx & 3;
                uint32_t doff = (uint32_t)(n * 64 + ((ch ^ ((n >> 1) & 3)) << 4));
                cpasync16(sb + stg1 + K1_B + doff, g_W1H + (size_t)n * D2 + k0n + ch * 8);
            }
            cpcommit();
            pa0 = *(const float4*)(aptr + k0n);
            pa1 = *(const float4*)(aptr + k0n + 4);
        }
        #pragma unroll
        for (int kstep = 0; kstep < 2; kstep++) {
            uint32_t ah[2][4];
            #pragma unroll
            for (int mi = 0; mi < 2; mi++) {
                int r = wm + mi * 16 + (lane & 15);
                int ch = kstep * 2 + (lane >> 4);
                uint32_t off = (uint32_t)(r * 64 + ((ch ^ ((r >> 1) & 3)) << 4));
                ldsm4(ah[mi], sb + K1_A + stg + off);
            }
            #pragma unroll
            for (int q = 0; q < 6; q++) {
                uint32_t bh[4];
                int n = wn + q * 16 + (lane & 7) + ((lane >> 4) << 3);
                int ch = kstep * 2 + ((lane >> 3) & 1);
                uint32_t off = (uint32_t)(n * 64 + ((ch ^ ((n >> 1) & 3)) << 4));
                ldsm4(bh, sb + K1_B + stg + off);
                #pragma unroll
                for (int mi = 0; mi < 2; mi++)
                    #pragma unroll
                    for (int j = 0; j < 2; j++)
                        mma16816(c[mi][q * 2 + j], ah[mi], &bh[j * 2]);
            }
        }
        if (cch < 31) {
            uint32_t stg1 = (uint32_t)((s ^ 1) * K1_STG);
            *(uint4*)(sm + K1_A + stg1 + a_sts) =
                make_uint4(f2h2(pa0.x, pa0.y), f2h2(pa0.z, pa0.w), f2h2(pa1.x, pa1.y), f2h2(pa1.z, pa1.w));
        }
    }

    // ---- tensor-core fused s2 epilogue ----
    __syncthreads();
    // S: [64 rows][384 halfs], stride EP_STRB bytes
    #pragma unroll
    for (int mi = 0; mi < 2; mi++) {
        int lr = wm + mi * 16 + (lane >> 2);
        #pragma unroll
        for (int cj = 0; cj < 12; cj++) {
            int ng = wn + cj * 8 + (lane & 3) * 2;
            int ngc0 = ng < DA_PAD ? ng : DA_PAD - 1;
            int ngc1 = (ng + 1) < DA_PAD ? (ng + 1) : DA_PAD - 1;
            float cc0 = g_catc[b * DA_PAD + ngc0];
            float cc1 = g_catc[b * DA_PAD + ngc1];
            *(uint32_t*)(sm + lr * EP_STRB + ng * 2) =
                f2h2(tanhf(c[mi][cj][0] + cc0), tanhf(c[mi][cj][1] + cc1));
            *(uint32_t*)(sm + (lr + 8) * EP_STRB + ng * 2) =
                f2h2(tanhf(c[mi][cj][2] + cc0), tanhf(c[mi][cj][3] + cc1));
        }
    }
    // stage W2H [32][384] fp16
    #pragma unroll
    for (int i = 0; i < 6; i++) {
        int idx = t + i * 256;            // < 1536 uint4
        int r = idx / 48, seg = idx - r * 48;
        *(uint4*)(sm + EP_W2 + r * EP_STRB + seg * 16) = *(const uint4*)(g_W2H + r * 384 + seg * 8);
    }
    __syncthreads();

    float c2[2][4];
    #pragma unroll
    for (int j = 0; j < 2; j++)
        #pragma unroll
        for (int q = 0; q < 4; q++) c2[j][q] = 0.f;
    int m0w = (wid & 3) * 16, rb = (wid >> 2) * 16;
    #pragma unroll 4
    for (int k0 = 0; k0 < 384; k0 += 16) {
        uint32_t aS[4], bW[4];
        ldsm4(aS, sb + (m0w + (lane & 15)) * EP_STRB + (k0 + (lane >> 4) * 8) * 2);
        ldsm4(bW, sb + EP_W2 + (rb + (lane & 7) + ((lane >> 4) << 3)) * EP_STRB
                      + (k0 + ((lane >> 3) & 1) * 8) * 2);
        mma16816(c2[0], aS, &bW[0]);
        mma16816(c2[1], aS, &bW[2]);
    }
    #pragma unroll
    for (int j = 0; j < 2; j++)
        #pragma unroll
        for (int q = 0; q < 4; q++) {
            int r = rb + j * 8 + (lane & 3) * 2 + (q & 1);
            int md = m0 + m0w + (lane >> 2) + (q >> 1) * 8;
            if (r < RR) g_s2[((size_t)b * RR + r) * SEQ + (md & 1023)] = c2[j][q];
        }
}

// ======================================================================
// K3: masked softmax; writes A (fp32 out) + probs fp16 (g_AH)
// ======================================================================
__global__ void k3_softmax(const int* __restrict__ len, float* __restrict__ outA) {
    __shared__ float sred[8];
    int br = blockIdx.x;
    int b = br / RR;
    int r = br - b * RR;
    int t = threadIdx.x;
    int lane = t & 31, warp = t >> 5;
    const float* src = g_s2 + (size_t)br * SEQ;
    int L = len[b];

    float4 v = *(const float4*)(src + t * 4);
    float vv[4] = {v.x, v.y, v.z, v.w};
    #pragma unroll
    for (int j = 0; j < 4; j++) if (t * 4 + j >= L) vv[j] = NEGV;

    float mx = fmaxf(fmaxf(vv[0], vv[1]), fmaxf(vv[2], vv[3]));
    #pragma unroll
    for (int o = 16; o; o >>= 1) mx = fmaxf(mx, __shfl_xor_sync(0xffffffffu, mx, o));
    if (lane == 0) sred[warp] = mx;
    __syncthreads();
    mx = sred[0];
    #pragma unroll
    for (int w = 1; w < 8; w++) mx = fmaxf(mx, sred[w]);

    float e[4], s = 0.f;
    #pragma unroll
    for (int j = 0; j < 4; j++) { e[j] = __expf(vv[j] - mx); s += e[j]; }
    #pragma unroll
    for (int o = 16; o; o >>= 1) s += __shfl_xor_sync(0xffffffffu, s, o);
    __syncthreads();
    if (lane == 0) sred[warp] = s;
    __syncthreads();
    s = 0.f;
    #pragma unroll
    for (int w = 0; w < 8; w++) s += sred[w];
    float inv = 1.f / s;

    float p0 = e[0] * inv, p1 = e[1] * inv, p2 = e[2] * inv, p3 = e[3] * inv;
    *(float4*)(outA + (size_t)br * SEQ + t * 4) = make_float4(p0, p1, p2, p3);
    *(uint2*)(g_AH + ((size_t)b * 32 + r) * SEQ + t * 4) =
        make_uint2(f2h2(p0, p1), f2h2(p2, p3));
}

// ======================================================================
// K4: M_enc = A @ enc via fp16 tensor cores.
//     A-op = enc^T (ldmatrix.trans from [n][d] fp16 smem), B-op = probs.
//     grid (8 dtiles, 64 b), 256 thr (8 warps x d16).
// ======================================================================
#define K4_ENCSTR 272
#define K4_PRBSTR 80
#define K4_PRB   8704
#define K4_STGSZ 11264

__global__ void __launch_bounds__(256) k4_mgemm(const float* __restrict__ enc) {
    __shared__ __align__(128) char sm4[2 * K4_STGSZ];
    uint32_t sb4 = smem_u32(sm4);
    int t = threadIdx.x;
    int lane = t & 31, wid = t >> 5;
    int dtile = blockIdx.x, b = blockIdx.y;
    const float* Eb = enc + (size_t)b * SEQ * D2 + dtile * 128;
    const __half* Ap = g_AH + ((size_t)b * 32 + (t >> 3)) * SEQ + (t & 7) * 4;

    float c[4][4];
    #pragma unroll
    for (int i = 0; i < 4; i++)
        #pragma unroll
        for (int q = 0; q < 4; q++) c[i][q] = 0.f;

    // prefetch chunk 0
    float4 pe[4];
    uint2 pp = *(const uint2*)(Ap);
    #pragma unroll
    for (int li = 0; li < 4; li++) {
        int idx = t + li * 256;
        pe[li] = *(const float4*)(Eb + (size_t)(idx >> 5) * D2 + (idx & 31) * 4);
    }

    for (int n0 = 0; n0 < SEQ; n0 += 32) {
        int s = (n0 >> 5) & 1;
        uint32_t base = (uint32_t)(s * K4_STGSZ);
        // STS stage s from regs
        *(uint2*)(sm4 + base + K4_PRB + (t >> 3) * K4_PRBSTR + (t & 7) * 8) = pp;
        #pragma unroll
        for (int li = 0; li < 4; li++) {
            int idx = t + li * 256;
            *(uint2*)(sm4 + base + (idx >> 5) * K4_ENCSTR + (idx & 31) * 8) = cvt4h(pe[li]);
        }
        __syncthreads();
        if (n0 + 32 < SEQ) {
            pp = *(const uint2*)(Ap + n0 + 32);
            #pragma unroll
            for (int li = 0; li < 4; li++) {
                int idx = t + li * 256;
                pe[li] = *(const float4*)(Eb + (size_t)(n0 + 32 + (idx >> 5)) * D2 + (idx & 31) * 4);
            }
        }
        #pragma unroll
        for (int ks = 0; ks < 2; ks++) {
            int kk = ks * 16;
            uint32_t ae[4], bp[8];
            ldsm4t(ae, sb4 + base + (kk + (lane & 7) + ((lane >> 4) << 3)) * K4_ENCSTR
                          + (wid * 16 + ((lane >> 3) & 1) * 8) * 2);
            uint32_t bpr = sb4 + base + K4_PRB
                          + ((lane & 7) + ((lane >> 4) << 3)) * K4_PRBSTR
                          + kk * 2 + ((lane >> 3) & 1) * 16;
            ldsm4(bp, bpr);
            ldsm4(bp + 4, bpr + 16 * K4_PRBSTR);
            mma16816(c[0], ae, &bp[0]);
            mma16816(c[1], ae, &bp[2]);
            mma16816(c[2], ae, &bp[4]);
            mma16816(c[3], ae, &bp[6]);
        }
    }

    // store M -> g_BM fp16 (r < 30 only)
    #pragma unroll
    for (int nj = 0; nj < 4; nj++)
        #pragma unroll
        for (int q = 0; q < 4; q++) {
            int r = nj * 8 + (lane & 3) * 2 + (q & 1);
            if (r < RR) {
                int d = dtile * 128 + wid * 16 + (lane >> 2) + (q >> 1) * 8;
                g_BM[(size_t)b * KMLP + (size_t)r * D3 + d] = __float2half_rn(c[nj][q]);
            }
        }
}

// ======================================================================
// K5b: fill cat part of BM (exact: softmax rows sum to 1)
// ======================================================================
__global__ void k5b_cat(const float* __restrict__ cat) {
    int idx = (blockIdx.x * 256 + threadIdx.x) * 4;
    int b = idx / (RR * DCAT);
    int rem = idx - b * RR * DCAT;
    int r = rem >> 9, d = rem & 511;
    float4 v = *(const float4*)(cat + (size_t)b * DCAT + d);
    size_t o = (size_t)b * KMLP + (size_t)r * D3 + D2 + d;
    *(uint2*)(g_BM + o) = cvt4h(v);
}

// ======================================================================
// K6: fp16 mma.sync split-K GEMM, double-buffered (unchanged from R7).
// ======================================================================
#define K6_STG 24576
#define K6_W   0
#define K6_B   16384
#define K6_SMEM 49152

__global__ void __launch_bounds__(256, 1) k6_mlp(const float* __restrict__ Wm) {
    extern __shared__ __align__(128) char sm[];
    uint32_t sb = smem_u32(sm);
    int t = threadIdx.x;
    int lane = t & 31, wid = t >> 5;
    int j0 = blockIdx.x * 128;
    int ks = blockIdx.y;
    int kbeg = ks * KCHUNK;
    int wj = (wid >> 2) * 64;
    int wb = (wid & 3) * 16;

    float c[4][2][4];
    #pragma unroll
    for (int i = 0; i < 4; i++)
        #pragma unroll
        for (int j = 0; j < 2; j++)
            #pragma unroll
            for (int q = 0; q < 4; q++) c[i][j][q] = 0.f;

    float4 wreg[8];
    #pragma unroll
    for (int i = 0; i < 2; i++) {
        int idx = t + i * 256;
        int row = idx >> 3, seg = idx & 7;
        uint32_t doff = (uint32_t)(row * 128 + ((seg * 16) ^ ((row & 7) << 4)));
        cpasync16(sb + K6_B + doff, g_BM + (size_t)row * KMLP + kbeg + seg * 8);
    }
    cpcommit();
    #pragma unroll
    for (int li = 0; li < 8; li++) {
        int idx = t + li * 256;
        wreg[li] = *(const float4*)(Wm + (size_t)(j0 + (idx >> 4)) * KMLP + kbeg + (idx & 15) * 4);
    }
    #pragma unroll
    for (int li = 0; li < 8; li++) {
        int idx = t + li * 256;
        int row = idx >> 4, seg = idx & 15;
        uint32_t byte = (uint32_t)(row * 128 + ((seg * 8) ^ ((row & 7) << 4)));
        *(uint2*)(sm + K6_W + byte) = cvt4h(wreg[li]);
    }

    int arow_l = lane & 15;
    int acol_l = (lane >> 4) * 16;
    int brow_l = (lane & 7) + ((lane >> 4) << 3);
    int bcol_l = ((lane >> 3) & 1) * 16;

    for (int cch = 0; cch < NCH6; cch++) {
        int s = cch & 1;
        uint32_t stg = (uint32_t)(s * K6_STG);
        cpwait0();
        __syncthreads();
        if (cch < NCH6 - 1) {
            uint32_t stg1 = (uint32_t)((s ^ 1) * K6_STG);
            int k0n = kbeg + (cch + 1) * 64;
            #pragma unroll
            for (int i = 0; i < 2; i++) {
                int idx = t + i * 256;
                int row = idx >> 3, seg = idx & 7;
                uint32_t doff = (uint32_t)(row * 128 + ((seg * 16) ^ ((row & 7) << 4)));
                cpasync16(sb + stg1 + K6_B + doff, g_BM + (size_t)row * KMLP + k0n + seg * 8);
            }
            cpcommit();
            #pragma unroll
            for (int li = 0; li < 8; li++) {
                int idx = t + li * 256;
                wreg[li] = *(const float4*)(Wm + (size_t)(j0 + (idx >> 4)) * KMLP + k0n + (idx & 15) * 4);
            }
        }
        #pragma unroll
        for (int ksp = 0; ksp < 4; ksp++) {
            int kb = ksp * 32;
            uint32_t ah[4][4], bh[4];
            #pragma unroll
            for (int mi = 0; mi < 4; mi++) {
                int row = wj + mi * 16 + arow_l;
                uint32_t off = (uint32_t)(row * 128 + ((kb + acol_l) ^ ((row & 7) << 4)));
                ldsm4(ah[mi], sb + stg + K6_W + off);
            }
            {
                int row = wb + brow_l;
                uint32_t off = (uint32_t)(row * 128 + ((kb + bcol_l) ^ ((row & 7) << 4)));
                ldsm4(bh, sb + stg + K6_B + off);
            }
            #pragma unroll
            for (int mi = 0; mi < 4; mi++)
                #pragma unroll
                for (int j = 0; j < 2; j++)
                    mma16816(c[mi][j], ah[mi], &bh[j * 2]);
        }
        if (cch < NCH6 - 1) {
            uint32_t stg1 = (uint32_t)((s ^ 1) * K6_STG);
            #pragma unroll
            for (int li = 0; li < 8; li++) {
                int idx = t + li * 256;
                int row = idx >> 4, seg = idx & 15;
                uint32_t byte = (uint32_t)(row * 128 + ((seg * 8) ^ ((row & 7) << 4)));
                *(uint2*)(sm + stg1 + K6_W + byte) = cvt4h(wreg[li]);
            }
        }
    }

    #pragma unroll
    for (int mi = 0; mi < 4; mi++) {
        int jr = j0 + wj + mi * 16 + (lane >> 2);
        #pragma unroll
        for (int j = 0; j < 2; j++) {
            int bc = wb + j * 8 + (lane & 3) * 2;
            float* d0 = g_part + ((size_t)ks * MLPD + jr) * BATCH + bc;
            float* d1 = g_part + ((size_t)ks * MLPD + jr + 8) * BATCH + bc;
            d0[0] = c[mi][j][0]; d0[1] = c[mi][j][1];
            d1[0] = c[mi][j][2]; d1[1] = c[mi][j][3];
        }
    }
}

// ======================================================================
// K7: reduce split-K + bias -> d_out
// ======================================================================
__global__ void k7_reduce(const float* __restrict__ bias, float* __restrict__ out) {
    int idx = blockIdx.x * 256 + threadIdx.x;
    int j = idx >> 6, b = idx & 63;
    float s = bias[j];
    #pragma unroll
    for (int ks = 0; ks < KSPLIT; ks++)
        s += g_part[((size_t)ks * MLPD + j) * BATCH + b];
    out[(size_t)b * MLPD + j] = s;
}

// ======================================================================
extern "C" void kernel_launch(void* const* d_in, const int* in_sizes, int n_in,
                              void* d_out, int out_size) {
    const float* enc = nullptr;
    const int*   len = nullptr;
    const float* cat = nullptr;
    const float* W1 = nullptr;
    const float* W2 = nullptr;
    const float* Wm = nullptr;
    const float* bm = nullptr;
    for (int i = 0; i < n_in; i++) {
        switch (in_sizes[i]) {
            case 67108864: enc = (const float*)d_in[i]; break;
            case 64:       len = (const int*)d_in[i];   break;
            case 32768:    cat = (const float*)d_in[i]; break;
            case 537600:   W1  = (const float*)d_in[i]; break;
            case 10500:    W2  = (const float*)d_in[i]; break;
            case 94371840: Wm  = (const float*)d_in[i]; break;
            case 2048:     bm  = (const float*)d_in[i]; break;
            default: break;
        }
    }
    float* outf = (float*)d_out;
    float* outO = outf;
    float* outA = outf + BATCH * MLPD;

    cudaFuncSetAttribute(k1_s1s2, cudaFuncAttributeMaxDynamicSharedMemorySize, K1_SMEM);
    cudaFuncSetAttribute(k6_mlp, cudaFuncAttributeMaxDynamicSharedMemorySize, K6_SMEM);

    k0_catc   <<<BATCH, 256>>>(W1, cat);
    k0b_w1    <<<(NW1 * D2) / 256, 256>>>(W1);
    k0b2_w2   <<<48, 256>>>(W2);
    k1_s1s2   <<<ROWS / 64, 256, K1_SMEM>>>(enc);
    k3_softmax<<<BATCH * RR, 256>>>(len, outA);
    k4_mgemm  <<<dim3(8, BATCH), 256>>>(enc);
    k5b_cat   <<<(BATCH * RR * DCAT) / 1024, 256>>>(cat);
    k6_mlp    <<<dim3(MLPD / 128, KSPLIT), 256, K6_SMEM>>>(Wm);
    k7_reduce <<<(BATCH * MLPD) / 256, 256>>>(bm, outO);
}

// round 11
// speedup vs baseline: 4.7184x; 1.0926x over previous
#include <cuda_runtime.h>
#include <cuda_fp16.h>
#include <math.h>
#include <stdint.h>

#define BATCH 64
#define SEQ   1024
#define D2    1024
#define DCAT  512
#define D3    1536
#define DA    350
#define CATP  384
#define NW1   384
#define RR    30
#define MLPD  2048
#define KMLP  46080
#define ROWS  65536
#define NEGV  (-1e9f)
#define KSPLIT 18
#define KCHUNK 2560
#define NCH6   40

// ---------------- scratch ----------------
__device__ float g_catc[BATCH * CATP];                     // zero-init; cols >=350 stay 0
__device__ float g_s2[BATCH * RR * SEQ];
__device__ float g_part[KSPLIT * MLPD * BATCH];
__device__ __align__(128) __half g_W1H[NW1 * D2];
__device__ __align__(128) __half g_W2H[32 * 384];          // [r pad 32][n pad 384]
__device__ __align__(128) __half g_AH[BATCH * 32 * SEQ];   // probs fp16, rows 30,31 zero
__device__ __align__(128) __half g_BM[BATCH * KMLP];
__device__ __align__(128) __half g_encH[(size_t)ROWS * D2];

// ---------------- helpers ----------------
__device__ __forceinline__ uint32_t smem_u32(const void* p) {
    uint32_t r;
    asm("{ .reg .u64 t; cvta.to.shared.u64 t, %1; cvt.u32.u64 %0, t; }" : "=r"(r) : "l"(p));
    return r;
}
__device__ __forceinline__ void ldsm4(uint32_t* r, uint32_t addr) {
    asm volatile("ldmatrix.sync.aligned.m8n8.x4.shared.b16 {%0,%1,%2,%3}, [%4];"
                 : "=r"(r[0]), "=r"(r[1]), "=r"(r[2]), "=r"(r[3]) : "r"(addr));
}
__device__ __forceinline__ void ldsm4t(uint32_t* r, uint32_t addr) {
    asm volatile("ldmatrix.sync.aligned.m8n8.x4.trans.shared.b16 {%0,%1,%2,%3}, [%4];"
                 : "=r"(r[0]), "=r"(r[1]), "=r"(r[2]), "=r"(r[3]) : "r"(addr));
}
__device__ __forceinline__ void mma16816(float* c, const uint32_t* a, const uint32_t* b) {
    asm volatile(
        "mma.sync.aligned.m16n8k16.row.col.f32.f16.f16.f32 "
        "{%0,%1,%2,%3}, {%4,%5,%6,%7}, {%8,%9}, {%0,%1,%2,%3};"
        : "+f"(c[0]), "+f"(c[1]), "+f"(c[2]), "+f"(c[3])
        : "r"(a[0]), "r"(a[1]), "r"(a[2]), "r"(a[3]), "r"(b[0]), "r"(b[1]));
}
__device__ __forceinline__ void cpasync16(uint32_t dst, const void* src) {
    asm volatile("cp.async.cg.shared.global [%0], [%1], 16;" :: "r"(dst), "l"(src));
}
__device__ __forceinline__ void cpcommit() { asm volatile("cp.async.commit_group;"); }
__device__ __forceinline__ void cpwait0()  { asm volatile("cp.async.wait_group 0;"); }

__device__ __forceinline__ uint32_t f2h2(float a, float b) {
    return (uint32_t)__half_as_ushort(__float2half_rn(a)) |
           ((uint32_t)__half_as_ushort(__float2half_rn(b)) << 16);
}
__device__ __forceinline__ uint2 cvt4h(float4 v) {
    return make_uint2(f2h2(v.x, v.y), f2h2(v.z, v.w));
}

// ======================================================================
// K0: catc[b,a] = W1_cat[a,:] . cat_emb[b,:]
// ======================================================================
__global__ void k0_catc(const float* __restrict__ W1, const float* __restrict__ cat) {
    int b = blockIdx.x;
    int warp = threadIdx.x >> 5, lane = threadIdx.x & 31;
    const float* cb = cat + b * DCAT;
    for (int a = warp; a < DA; a += 8) {
        const float* w = W1 + (size_t)a * D3 + D2;
        float s = 0.f;
        for (int d = lane; d < DCAT; d += 32) s += w[d] * cb[d];
        #pragma unroll
        for (int o = 16; o; o >>= 1) s += __shfl_xor_sync(0xffffffffu, s, o);
        if (lane == 0) g_catc[b * CATP + a] = s;
    }
}

// ======================================================================
// K0b: W1 -> fp16 [384][1024]; K0b2: W2 -> fp16 [32][384]
// K0c: enc -> fp16; K0z: zero g_s2
// ======================================================================
__global__ void k0b_w1(const float* __restrict__ W1) {
    int i = blockIdx.x * 256 + threadIdx.x;
    int row = i >> 10, k = i & 1023;
    float v = (row < DA) ? W1[(size_t)row * D3 + k] : 0.f;
    g_W1H[i] = __float2half_rn(v);
}
__global__ void k0b2_w2(const float* __restrict__ W2) {
    int i = blockIdx.x * 256 + threadIdx.x;   // < 12288
    int r = i / 384, n = i - r * 384;
    float v = (r < RR && n < DA) ? W2[r * DA + n] : 0.f;
    g_W2H[i] = __float2half_rn(v);
}
__global__ void k0c_enc(const float* __restrict__ enc) {
    size_t i = ((size_t)blockIdx.x * 256 + threadIdx.x) * 8;
    float4 v0 = *(const float4*)(enc + i);
    float4 v1 = *(const float4*)(enc + i + 4);
    *(uint4*)(g_encH + i) = make_uint4(f2h2(v0.x, v0.y), f2h2(v0.z, v0.w),
                                       f2h2(v1.x, v1.y), f2h2(v1.z, v1.w));
}
__global__ void k0z_zero() {
    int i = blockIdx.x * 256 + threadIdx.x;   // < 491520
    *(float4*)(g_s2 + (size_t)i * 4) = make_float4(0.f, 0.f, 0.f, 0.f);
}

// ======================================================================
// K1: fp16 mma.sync GEMM, CTA tile 64(M) x 192(N), K chunks of 32,
//     both operands cp.async double-buffered, 2 CTAs/SM.
//     Fused partial-s2 epilogue (tensor core) -> atomicAdd into g_s2.
//     grid (2 ntile, 1024 mtile), 256 thr (8 warps: 2m x 4n, warp 32x48).
// ======================================================================
#define K1_STG   16384
#define K1_A     0
#define K1_B     4096
#define EP_STR   400                        // 192 halfs + pad, bytes
#define EP_W2    25600                      // 64*400
#define K1_SMEM  38400                      // max(2*16384, 25600+32*400)

__global__ void __launch_bounds__(256, 2) k1_s1s2() {
    extern __shared__ __align__(128) char sm[];
    uint32_t sb = smem_u32(sm);
    int t = threadIdx.x;
    int lane = t & 31, wid = t >> 5;
    int n0g = blockIdx.x * 192;
    int m0 = blockIdx.y * 64;
    int b = m0 >> 10;
    int wm = (wid >> 2) * 32;
    int wn = (wid & 3) * 48;

    float c[2][6][4];
    #pragma unroll
    for (int i = 0; i < 2; i++)
        #pragma unroll
        for (int j = 0; j < 6; j++)
            #pragma unroll
            for (int q = 0; q < 4; q++) c[i][j][q] = 0.f;

    // A: row ar = t>>2 (64), 16B seg ac = t&3 (covers K=32 halves)
    int ar = t >> 2, ac = t & 3;
    const __half* aptr = g_encH + (size_t)(m0 + ar) * D2 + ac * 8;
    uint32_t a_sts = (uint32_t)(ar * 64 + ((ac ^ ((ar >> 1) & 3)) << 4));

    // prologue: chunk 0
    cpasync16(sb + K1_A + a_sts, aptr);
    #pragma unroll
    for (int i = 0; i < 3; i++) {
        int idx = t + i * 256;               // < 768
        int n = idx >> 2, ch = idx & 3;
        uint32_t doff = (uint32_t)(n * 64 + ((ch ^ ((n >> 1) & 3)) << 4));
        cpasync16(sb + K1_B + doff, g_W1H + (size_t)(n0g + n) * D2 + ch * 8);
    }
    cpcommit();

    for (int cch = 0; cch < 32; cch++) {
        int s = cch & 1;
        uint32_t stg = (uint32_t)(s * K1_STG);
        cpwait0();
        __syncthreads();
        if (cch < 31) {
            uint32_t stg1 = (uint32_t)((s ^ 1) * K1_STG);
            int k0n = (cch + 1) * 32;
            cpasync16(sb + stg1 + K1_A + a_sts, aptr + k0n);
            #pragma unroll
            for (int i = 0; i < 3; i++) {
                int idx = t + i * 256;
                int n = idx >> 2, ch = idx & 3;
                uint32_t doff = (uint32_t)(n * 64 + ((ch ^ ((n >> 1) & 3)) << 4));
                cpasync16(sb + stg1 + K1_B + doff, g_W1H + (size_t)(n0g + n) * D2 + k0n + ch * 8);
            }
            cpcommit();
        }
        #pragma unroll
        for (int kstep = 0; kstep < 2; kstep++) {
            uint32_t ah[2][4];
            #pragma unroll
            for (int mi = 0; mi < 2; mi++) {
                int r = wm + mi * 16 + (lane & 15);
                int ch = kstep * 2 + (lane >> 4);
                uint32_t off = (uint32_t)(r * 64 + ((ch ^ ((r >> 1) & 3)) << 4));
                ldsm4(ah[mi], sb + K1_A + stg + off);
            }
            #pragma unroll
            for (int q = 0; q < 3; q++) {
                uint32_t bh[4];
                int n = wn + q * 16 + (lane & 7) + ((lane >> 4) << 3);
                int ch = kstep * 2 + ((lane >> 3) & 1);
                uint32_t off = (uint32_t)(n * 64 + ((ch ^ ((n >> 1) & 3)) << 4));
                ldsm4(bh, sb + K1_B + stg + off);
                #pragma unroll
                for (int mi = 0; mi < 2; mi++)
                    #pragma unroll
                    for (int j = 0; j < 2; j++)
                        mma16816(c[mi][q * 2 + j], ah[mi], &bh[j * 2]);
            }
        }
    }

    // ---- fused partial-s2 epilogue (this CTA's 192 columns) ----
    __syncthreads();
    // S: [64][192] halfs @0 stride EP_STR; W2 slice [32][192] @EP_W2
    #pragma unroll
    for (int mi = 0; mi < 2; mi++) {
        int lr = wm + mi * 16 + (lane >> 2);
        #pragma unroll
        for (int cj = 0; cj < 6; cj++) {
            int ng = wn + cj * 8 + (lane & 3) * 2;
            float cc0 = g_catc[b * CATP + n0g + ng];
            float cc1 = g_catc[b * CATP + n0g + ng + 1];
            *(uint32_t*)(sm + lr * EP_STR + ng * 2) =
                f2h2(tanhf(c[mi][cj][0] + cc0), tanhf(c[mi][cj][1] + cc1));
            *(uint32_t*)(sm + (lr + 8) * EP_STR + ng * 2) =
                f2h2(tanhf(c[mi][cj][2] + cc0), tanhf(c[mi][cj][3] + cc1));
        }
    }
    #pragma unroll
    for (int i = 0; i < 3; i++) {
        int idx = t + i * 256;               // < 768
        int r = idx / 24, seg = idx - r * 24;
        *(uint4*)(sm + EP_W2 + r * EP_STR + seg * 16) =
            *(const uint4*)(g_W2H + r * 384 + n0g + seg * 8);
    }
    __syncthreads();

    float c2[2][4];
    #pragma unroll
    for (int j = 0; j < 2; j++)
        #pragma unroll
        for (int q = 0; q < 4; q++) c2[j][q] = 0.f;
    int m0w = (wid & 3) * 16, rb = (wid >> 2) * 16;
    #pragma unroll
    for (int k0 = 0; k0 < 192; k0 += 16) {
        uint32_t aS[4], bW[4];
        ldsm4(aS, sb + (m0w + (lane & 15)) * EP_STR + (k0 + (lane >> 4) * 8) * 2);
        ldsm4(bW, sb + EP_W2 + (rb + (lane & 7) + ((lane >> 4) << 3)) * EP_STR
                      + (k0 + ((lane >> 3) & 1) * 8) * 2);
        mma16816(c2[0], aS, &bW[0]);
        mma16816(c2[1], aS, &bW[2]);
    }
    #pragma unroll
    for (int j = 0; j < 2; j++)
        #pragma unroll
        for (int q = 0; q < 4; q++) {
            int r = rb + j * 8 + (lane & 3) * 2 + (q & 1);
            int md = m0 + m0w + (lane >> 2) + (q >> 1) * 8;
            if (r < RR)
                atomicAdd(&g_s2[((size_t)b * RR + r) * SEQ + (md & 1023)], c2[j][q]);
        }
}

// ======================================================================
// K3: masked softmax; writes A (fp32 out) + probs fp16 (g_AH)
// ======================================================================
__global__ void k3_softmax(const int* __restrict__ len, float* __restrict__ outA) {
    __shared__ float sred[8];
    int br = blockIdx.x;
    int b = br / RR;
    int r = br - b * RR;
    int t = threadIdx.x;
    int lane = t & 31, warp = t >> 5;
    const float* src = g_s2 + (size_t)br * SEQ;
    int L = len[b];

    float4 v = *(const float4*)(src + t * 4);
    float vv[4] = {v.x, v.y, v.z, v.w};
    #pragma unroll
    for (int j = 0; j < 4; j++) if (t * 4 + j >= L) vv[j] = NEGV;

    float mx = fmaxf(fmaxf(vv[0], vv[1]), fmaxf(vv[2], vv[3]));
    #pragma unroll
    for (int o = 16; o; o >>= 1) mx = fmaxf(mx, __shfl_xor_sync(0xffffffffu, mx, o));
    if (lane == 0) sred[warp] = mx;
    __syncthreads();
    mx = sred[0];
    #pragma unroll
    for (int w = 1; w < 8; w++) mx = fmaxf(mx, sred[w]);

    float e[4], s = 0.f;
    #pragma unroll
    for (int j = 0; j < 4; j++) { e[j] = __expf(vv[j] - mx); s += e[j]; }
    #pragma unroll
    for (int o = 16; o; o >>= 1) s += __shfl_xor_sync(0xffffffffu, s, o);
    __syncthreads();
    if (lane == 0) sred[warp] = s;
    __syncthreads();
    s = 0.f;
    #pragma unroll
    for (int w = 0; w < 8; w++) s += sred[w];
    float inv = 1.f / s;

    float p0 = e[0] * inv, p1 = e[1] * inv, p2 = e[2] * inv, p3 = e[3] * inv;
    *(float4*)(outA + (size_t)br * SEQ + t * 4) = make_float4(p0, p1, p2, p3);
    *(uint2*)(g_AH + ((size_t)b * 32 + r) * SEQ + t * 4) =
        make_uint2(f2h2(p0, p1), f2h2(p2, p3));
}

// ======================================================================
// K4: M_enc = A @ enc via fp16 tensor cores, enc read as fp16 directly.
// ======================================================================
#define K4_ENCSTR 272
#define K4_PRBSTR 80
#define K4_PRB   8704
#define K4_STGSZ 11264

__global__ void __launch_bounds__(256) k4_mgemm() {
    __shared__ __align__(128) char sm4[2 * K4_STGSZ];
    uint32_t sb4 = smem_u32(sm4);
    int t = threadIdx.x;
    int lane = t & 31, wid = t >> 5;
    int dtile = blockIdx.x, b = blockIdx.y;
    const __half* Eb = g_encH + (size_t)b * SEQ * D2 + dtile * 128;
    const __half* Ap = g_AH + ((size_t)b * 32 + (t >> 3)) * SEQ + (t & 7) * 4;

    float c[4][4];
    #pragma unroll
    for (int i = 0; i < 4; i++)
        #pragma unroll
        for (int q = 0; q < 4; q++) c[i][q] = 0.f;

    uint2 pe[4];
    uint2 pp = *(const uint2*)(Ap);
    #pragma unroll
    for (int li = 0; li < 4; li++) {
        int idx = t + li * 256;
        pe[li] = *(const uint2*)(Eb + (size_t)(idx >> 5) * D2 + (idx & 31) * 4);
    }

    for (int n0 = 0; n0 < SEQ; n0 += 32) {
        int s = (n0 >> 5) & 1;
        uint32_t base = (uint32_t)(s * K4_STGSZ);
        *(uint2*)(sm4 + base + K4_PRB + (t >> 3) * K4_PRBSTR + (t & 7) * 8) = pp;
        #pragma unroll
        for (int li = 0; li < 4; li++) {
            int idx = t + li * 256;
            *(uint2*)(sm4 + base + (idx >> 5) * K4_ENCSTR + (idx & 31) * 8) = pe[li];
        }
        __syncthreads();
        if (n0 + 32 < SEQ) {
            pp = *(const uint2*)(Ap + n0 + 32);
            #pragma unroll
            for (int li = 0; li < 4; li++) {
                int idx = t + li * 256;
                pe[li] = *(const uint2*)(Eb + (size_t)(n0 + 32 + (idx >> 5)) * D2 + (idx & 31) * 4);
            }
        }
        #pragma unroll
        for (int ks = 0; ks < 2; ks++) {
            int kk = ks * 16;
            uint32_t ae[4], bp[8];
            ldsm4t(ae, sb4 + base + (kk + (lane & 7) + ((lane >> 4) << 3)) * K4_ENCSTR
                          + (wid * 16 + ((lane >> 3) & 1) * 8) * 2);
            uint32_t bpr = sb4 + base + K4_PRB
                          + ((lane & 7) + ((lane >> 4) << 3)) * K4_PRBSTR
                          + kk * 2 + ((lane >> 3) & 1) * 16;
            ldsm4(bp, bpr);
            ldsm4(bp + 4, bpr + 16 * K4_PRBSTR);
            mma16816(c[0], ae, &bp[0]);
            mma16816(c[1], ae, &bp[2]);
            mma16816(c[2], ae, &bp[4]);
            mma16816(c[3], ae, &bp[6]);
        }
    }

    #pragma unroll
    for (int nj = 0; nj < 4; nj++)
        #pragma unroll
        for (int q = 0; q < 4; q++) {
            int r = nj * 8 + (lane & 3) * 2 + (q & 1);
            if (r < RR) {
                int d = dtile * 128 + wid * 16 + (lane >> 2) + (q >> 1) * 8;
                g_BM[(size_t)b * KMLP + (size_t)r * D3 + d] = __float2half_rn(c[nj][q]);
            }
        }
}

// ======================================================================
// K5b: fill cat part of BM (exact: softmax rows sum to 1)
// ======================================================================
__global__ void k5b_cat(const float* __restrict__ cat) {
    int idx = (blockIdx.x * 256 + threadIdx.x) * 4;
    int b = idx / (RR * DCAT);
    int rem = idx - b * RR * DCAT;
    int r = rem >> 9, d = rem & 511;
    float4 v = *(const float4*)(cat + (size_t)b * DCAT + d);
    size_t o = (size_t)b * KMLP + (size_t)r * D3 + D2 + d;
    *(uint2*)(g_BM + o) = cvt4h(v);
}

// ======================================================================
// K6: fp16 mma.sync split-K GEMM, double-buffered (unchanged).
// ======================================================================
#define K6_STG 24576
#define K6_W   0
#define K6_B   16384
#define K6_SMEM 49152

__global__ void __launch_bounds__(256, 1) k6_mlp(const float* __restrict__ Wm) {
    extern __shared__ __align__(128) char sm[];
    uint32_t sb = smem_u32(sm);
    int t = threadIdx.x;
    int lane = t & 31, wid = t >> 5;
    int j0 = blockIdx.x * 128;
    int ks = blockIdx.y;
    int kbeg = ks * KCHUNK;
    int wj = (wid >> 2) * 64;
    int wb = (wid & 3) * 16;

    float c[4][2][4];
    #pragma unroll
    for (int i = 0; i < 4; i++)
        #pragma unroll
        for (int j = 0; j < 2; j++)
            #pragma unroll
            for (int q = 0; q < 4; q++) c[i][j][q] = 0.f;

    float4 wreg[8];
    #pragma unroll
    for (int i = 0; i < 2; i++) {
        int idx = t + i * 256;
        int row = idx >> 3, seg = idx & 7;
        uint32_t doff = (uint32_t)(row * 128 + ((seg * 16) ^ ((row & 7) << 4)));
        cpasync16(sb + K6_B + doff, g_BM + (size_t)row * KMLP + kbeg + seg * 8);
    }
    cpcommit();
    #pragma unroll
    for (int li = 0; li < 8; li++) {
        int idx = t + li * 256;
        wreg[li] = *(const float4*)(Wm + (size_t)(j0 + (idx >> 4)) * KMLP + kbeg + (idx & 15) * 4);
    }
    #pragma unroll
    for (int li = 0; li < 8; li++) {
        int idx = t + li * 256;
        int row = idx >> 4, seg = idx & 15;
        uint32_t byte = (uint32_t)(row * 128 + ((seg * 8) ^ ((row & 7) << 4)));
        *(uint2*)(sm + K6_W + byte) = cvt4h(wreg[li]);
    }

    int arow_l = lane & 15;
    int acol_l = (lane >> 4) * 16;
    int brow_l = (lane & 7) + ((lane >> 4) << 3);
    int bcol_l = ((lane >> 3) & 1) * 16;

    for (int cch = 0; cch < NCH6; cch++) {
        int s = cch & 1;
        uint32_t stg = (uint32_t)(s * K6_STG);
        cpwait0();
        __syncthreads();
        if (cch < NCH6 - 1) {
            uint32_t stg1 = (uint32_t)((s ^ 1) * K6_STG);
            int k0n = kbeg + (cch + 1) * 64;
            #pragma unroll
            for (int i = 0; i < 2; i++) {
                int idx = t + i * 256;
                int row = idx >> 3, seg = idx & 7;
                uint32_t doff = (uint32_t)(row * 128 + ((seg * 16) ^ ((row & 7) << 4)));
                cpasync16(sb + stg1 + K6_B + doff, g_BM + (size_t)row * KMLP + k0n + seg * 8);
            }
            cpcommit();
            #pragma unroll
            for (int li = 0; li < 8; li++) {
                int idx = t + li * 256;
                wreg[li] = *(const float4*)(Wm + (size_t)(j0 + (idx >> 4)) * KMLP + k0n + (idx & 15) * 4);
            }
        }
        #pragma unroll
        for (int ksp = 0; ksp < 4; ksp++) {
            int kb = ksp * 32;
            uint32_t ah[4][4], bh[4];
            #pragma unroll
            for (int mi = 0; mi < 4; mi++) {
                int row = wj + mi * 16 + arow_l;
                uint32_t off = (uint32_t)(row * 128 + ((kb + acol_l) ^ ((row & 7) << 4)));
                ldsm4(ah[mi], sb + stg + K6_W + off);
            }
            {
                int row = wb + brow_l;
                uint32_t off = (uint32_t)(row * 128 + ((kb + bcol_l) ^ ((row & 7) << 4)));
                ldsm4(bh, sb + stg + K6_B + off);
            }
            #pragma unroll
            for (int mi = 0; mi < 4; mi++)
                #pragma unroll
                for (int j = 0; j < 2; j++)
                    mma16816(c[mi][j], ah[mi], &bh[j * 2]);
        }
        if (cch < NCH6 - 1) {
            uint32_t stg1 = (uint32_t)((s ^ 1) * K6_STG);
            #pragma unroll
            for (int li = 0; li < 8; li++) {
                int idx = t + li * 256;
                int row = idx >> 4, seg = idx & 15;
                uint32_t byte = (uint32_t)(row * 128 + ((seg * 8) ^ ((row & 7) << 4)));
                *(uint2*)(sm + stg1 + K6_W + byte) = cvt4h(wreg[li]);
            }
        }
    }

    #pragma unroll
    for (int mi = 0; mi < 4; mi++) {
        int jr = j0 + wj + mi * 16 + (lane >> 2);
        #pragma unroll
        for (int j = 0; j < 2; j++) {
            int bc = wb + j * 8 + (lane & 3) * 2;
            float* d0 = g_part + ((size_t)ks * MLPD + jr) * BATCH + bc;
            float* d1 = g_part + ((size_t)ks * MLPD + jr + 8) * BATCH + bc;
            d0[0] = c[mi][j][0]; d0[1] = c[mi][j][1];
            d1[0] = c[mi][j][2]; d1[1] = c[mi][j][3];
        }
    }
}

// ======================================================================
// K7: reduce split-K + bias -> d_out
// ======================================================================
__global__ void k7_reduce(const float* __restrict__ bias, float* __restrict__ out) {
    int idx = blockIdx.x * 256 + threadIdx.x;
    int j = idx >> 6, b = idx & 63;
    float s = bias[j];
    #pragma unroll
    for (int ks = 0; ks < KSPLIT; ks++)
        s += g_part[((size_t)ks * MLPD + j) * BATCH + b];
    out[(size_t)b * MLPD + j] = s;
}

// ======================================================================
extern "C" void kernel_launch(void* const* d_in, const int* in_sizes, int n_in,
                              void* d_out, int out_size) {
    const float* enc = nullptr;
    const int*   len = nullptr;
    const float* cat = nullptr;
    const float* W1 = nullptr;
    const float* W2 = nullptr;
    const float* Wm = nullptr;
    const float* bm = nullptr;
    for (int i = 0; i < n_in; i++) {
        switch (in_sizes[i]) {
            case 67108864: enc = (const float*)d_in[i]; break;
            case 64:       len = (const int*)d_in[i];   break;
            case 32768:    cat = (const float*)d_in[i]; break;
            case 537600:   W1  = (const float*)d_in[i]; break;
            case 10500:    W2  = (const float*)d_in[i]; break;
            case 94371840: Wm  = (const float*)d_in[i]; break;
            case 2048:     bm  = (const float*)d_in[i]; break;
            default: break;
        }
    }
    float* outf = (float*)d_out;
    float* outO = outf;
    float* outA = outf + BATCH * MLPD;

    cudaFuncSetAttribute(k1_s1s2, cudaFuncAttributeMaxDynamicSharedMemorySize, K1_SMEM);
    cudaFuncSetAttribute(k6_mlp, cudaFuncAttributeMaxDynamicSharedMemorySize, K6_SMEM);

    k0_catc   <<<BATCH, 256>>>(W1, cat);
    k0b_w1    <<<(NW1 * D2) / 256, 256>>>(W1);
    k0b2_w2   <<<48, 256>>>(W2);
    k0c_enc   <<<32768, 256>>>(enc);
    k0z_zero  <<<1920, 256>>>();
    k1_s1s2   <<<dim3(2, ROWS / 64), 256, K1_SMEM>>>();
    k3_softmax<<<BATCH * RR, 256>>>(len, outA);
    k4_mgemm  <<<dim3(8, BATCH), 256>>>();
    k5b_cat   <<<(BATCH * RR * DCAT) / 1024, 256>>>(cat);
    k6_mlp    <<<dim3(MLPD / 128, KSPLIT), 256, K6_SMEM>>>(Wm);
    k7_reduce <<<(BATCH * MLPD) / 256, 256>>>(bm, outO);
}

// round 12
// speedup vs baseline: 5.1586x; 1.0933x over previous
#include <cuda_runtime.h>
#include <cuda_fp16.h>
#include <math.h>
#include <stdint.h>

#define BATCH 64
#define SEQ   1024
#define D2    1024
#define DCAT  512
#define D3    1536
#define DA    350
#define CATP  384
#define NW1   384
#define RR    30
#define MLPD  2048
#define KMLP  46080
#define ROWS  65536
#define NEGV  (-1e9f)
#define KSPLIT 18
#define KCHUNK 2560
#define NCH6   40

// ---------------- scratch ----------------
__device__ float g_catc[BATCH * CATP];                     // zero-init; cols >=350 stay 0
__device__ float g_s2[BATCH * RR * SEQ];
__device__ float g_part[KSPLIT * MLPD * BATCH];
__device__ __align__(128) __half g_W1H[NW1 * D2];
__device__ __align__(128) __half g_W2H[32 * 384];          // [r pad 32][n pad 384]
__device__ __align__(128) __half g_AH[BATCH * 32 * SEQ];   // probs fp16, rows 30,31 zero
__device__ __align__(128) __half g_BM[BATCH * KMLP];

// ---------------- helpers ----------------
__device__ __forceinline__ uint32_t smem_u32(const void* p) {
    uint32_t r;
    asm("{ .reg .u64 t; cvta.to.shared.u64 t, %1; cvt.u32.u64 %0, t; }" : "=r"(r) : "l"(p));
    return r;
}
__device__ __forceinline__ void ldsm4(uint32_t* r, uint32_t addr) {
    asm volatile("ldmatrix.sync.aligned.m8n8.x4.shared.b16 {%0,%1,%2,%3}, [%4];"
                 : "=r"(r[0]), "=r"(r[1]), "=r"(r[2]), "=r"(r[3]) : "r"(addr));
}
__device__ __forceinline__ void ldsm4t(uint32_t* r, uint32_t addr) {
    asm volatile("ldmatrix.sync.aligned.m8n8.x4.trans.shared.b16 {%0,%1,%2,%3}, [%4];"
                 : "=r"(r[0]), "=r"(r[1]), "=r"(r[2]), "=r"(r[3]) : "r"(addr));
}
__device__ __forceinline__ void mma16816(float* c, const uint32_t* a, const uint32_t* b) {
    asm volatile(
        "mma.sync.aligned.m16n8k16.row.col.f32.f16.f16.f32 "
        "{%0,%1,%2,%3}, {%4,%5,%6,%7}, {%8,%9}, {%0,%1,%2,%3};"
        : "+f"(c[0]), "+f"(c[1]), "+f"(c[2]), "+f"(c[3])
        : "r"(a[0]), "r"(a[1]), "r"(a[2]), "r"(a[3]), "r"(b[0]), "r"(b[1]));
}
__device__ __forceinline__ void cpasync16(uint32_t dst, const void* src) {
    asm volatile("cp.async.cg.shared.global [%0], [%1], 16;" :: "r"(dst), "l"(src));
}
__device__ __forceinline__ void cpcommit() { asm volatile("cp.async.commit_group;"); }
__device__ __forceinline__ void cpwait0()  { asm volatile("cp.async.wait_group 0;"); }

__device__ __forceinline__ uint32_t f2h2(float a, float b) {
    return (uint32_t)__half_as_ushort(__float2half_rn(a)) |
           ((uint32_t)__half_as_ushort(__float2half_rn(b)) << 16);
}
__device__ __forceinline__ uint2 cvt4h(float4 v) {
    return make_uint2(f2h2(v.x, v.y), f2h2(v.z, v.w));
}

// ======================================================================
// K0: catc[b,a] = W1_cat[a,:] . cat_emb[b,:]
// ======================================================================
__global__ void k0_catc(const float* __restrict__ W1, const float* __restrict__ cat) {
    int b = blockIdx.x;
    int warp = threadIdx.x >> 5, lane = threadIdx.x & 31;
    const float* cb = cat + b * DCAT;
    for (int a = warp; a < DA; a += 8) {
        const float* w = W1 + (size_t)a * D3 + D2;
        float s = 0.f;
        for (int d = lane; d < DCAT; d += 32) s += w[d] * cb[d];
        #pragma unroll
        for (int o = 16; o; o >>= 1) s += __shfl_xor_sync(0xffffffffu, s, o);
        if (lane == 0) g_catc[b * CATP + a] = s;
    }
}

// ======================================================================
// K0b: W1 -> fp16 [384][1024]; K0b2: W2 -> fp16 [32][384]; K0z: zero g_s2
// ======================================================================
__global__ void k0b_w1(const float* __restrict__ W1) {
    int i = blockIdx.x * 256 + threadIdx.x;
    int row = i >> 10, k = i & 1023;
    float v = (row < DA) ? W1[(size_t)row * D3 + k] : 0.f;
    g_W1H[i] = __float2half_rn(v);
}
__global__ void k0b2_w2(const float* __restrict__ W2) {
    int i = blockIdx.x * 256 + threadIdx.x;   // < 12288
    int r = i / 384, n = i - r * 384;
    float v = (r < RR && n < DA) ? W2[r * DA + n] : 0.f;
    g_W2H[i] = __float2half_rn(v);
}
__global__ void k0z_zero() {
    int i = blockIdx.x * 256 + threadIdx.x;   // < 491520
    *(float4*)(g_s2 + (size_t)i * 4) = make_float4(0.f, 0.f, 0.f, 0.f);
}

// ======================================================================
// K1: fp16 mma.sync GEMM, CTA tile 64(M) x 192(N), K chunks of 32.
//     A: enc fp32 -> fp16 in-register (reg-prefetch double buffer).
//     B: cp.async double-buffered. 2 CTAs/SM. Fused partial-s2 epilogue
//     (tensor core) -> atomicAdd into g_s2.
//     grid (2 ntile, 1024 mtile); paired n-tile CTAs share enc via L2.
// ======================================================================
#define K1_STG   16384
#define K1_A     0
#define K1_B     4096
#define EP_STR   400                        // 192 halfs + pad, bytes
#define EP_W2    25600                      // 64*400
#define K1_SMEM  38400                      // max(2*16384, 25600+32*400)

__global__ void __launch_bounds__(256, 2) k1_s1s2(const float* __restrict__ enc) {
    extern __shared__ __align__(128) char sm[];
    uint32_t sb = smem_u32(sm);
    int t = threadIdx.x;
    int lane = t & 31, wid = t >> 5;
    int n0g = blockIdx.x * 192;
    int m0 = blockIdx.y * 64;
    int b = m0 >> 10;
    int wm = (wid >> 2) * 32;
    int wn = (wid & 3) * 48;

    float c[2][6][4];
    #pragma unroll
    for (int i = 0; i < 2; i++)
        #pragma unroll
        for (int j = 0; j < 6; j++)
            #pragma unroll
            for (int q = 0; q < 4; q++) c[i][j][q] = 0.f;

    // A: row ar = t>>2 (64 rows), seg ac = t&3 (8 fp32 each -> 8 halves)
    int ar = t >> 2, ac = t & 3;
    const float* aptr = enc + (size_t)(m0 + ar) * D2 + ac * 8;
    uint32_t a_sts = (uint32_t)(ar * 64 + ((ac ^ ((ar >> 1) & 3)) << 4));

    // prologue: B chunk0 cp.async; A chunk0 via regs -> stage0
    #pragma unroll
    for (int i = 0; i < 3; i++) {
        int idx = t + i * 256;               // < 768
        int n = idx >> 2, ch = idx & 3;
        uint32_t doff = (uint32_t)(n * 64 + ((ch ^ ((n >> 1) & 3)) << 4));
        cpasync16(sb + K1_B + doff, g_W1H + (size_t)(n0g + n) * D2 + ch * 8);
    }
    cpcommit();
    float4 pa0 = *(const float4*)(aptr);
    float4 pa1 = *(const float4*)(aptr + 4);
    *(uint4*)(sm + K1_A + a_sts) =
        make_uint4(f2h2(pa0.x, pa0.y), f2h2(pa0.z, pa0.w), f2h2(pa1.x, pa1.y), f2h2(pa1.z, pa1.w));

    for (int cch = 0; cch < 32; cch++) {
        int s = cch & 1;
        uint32_t stg = (uint32_t)(s * K1_STG);
        cpwait0();
        __syncthreads();
        if (cch < 31) {
            uint32_t stg1 = (uint32_t)((s ^ 1) * K1_STG);
            int k0n = (cch + 1) * 32;
            #pragma unroll
            for (int i = 0; i < 3; i++) {
                int idx = t + i * 256;
                int n = idx >> 2, ch = idx & 3;
                uint32_t doff = (uint32_t)(n * 64 + ((ch ^ ((n >> 1) & 3)) << 4));
                cpasync16(sb + stg1 + K1_B + doff, g_W1H + (size_t)(n0g + n) * D2 + k0n + ch * 8);
            }
            cpcommit();
            pa0 = *(const float4*)(aptr + k0n);
            pa1 = *(const float4*)(aptr + k0n + 4);
        }
        #pragma unroll
        for (int kstep = 0; kstep < 2; kstep++) {
            uint32_t ah[2][4];
            #pragma unroll
            for (int mi = 0; mi < 2; mi++) {
                int r = wm + mi * 16 + (lane & 15);
                int ch = kstep * 2 + (lane >> 4);
                uint32_t off = (uint32_t)(r * 64 + ((ch ^ ((r >> 1) & 3)) << 4));
                ldsm4(ah[mi], sb + K1_A + stg + off);
            }
            #pragma unroll
            for (int q = 0; q < 3; q++) {
                uint32_t bh[4];
                int n = wn + q * 16 + (lane & 7) + ((lane >> 4) << 3);
                int ch = kstep * 2 + ((lane >> 3) & 1);
                uint32_t off = (uint32_t)(n * 64 + ((ch ^ ((n >> 1) & 3)) << 4));
                ldsm4(bh, sb + K1_B + stg + off);
                #pragma unroll
                for (int mi = 0; mi < 2; mi++)
                    #pragma unroll
                    for (int j = 0; j < 2; j++)
                        mma16816(c[mi][q * 2 + j], ah[mi], &bh[j * 2]);
            }
        }
        if (cch < 31) {
            uint32_t stg1 = (uint32_t)((s ^ 1) * K1_STG);
            *(uint4*)(sm + K1_A + stg1 + a_sts) =
                make_uint4(f2h2(pa0.x, pa0.y), f2h2(pa0.z, pa0.w),
                           f2h2(pa1.x, pa1.y), f2h2(pa1.z, pa1.w));
        }
    }

    // ---- fused partial-s2 epilogue (this CTA's 192 columns) ----
    __syncthreads();
    #pragma unroll
    for (int mi = 0; mi < 2; mi++) {
        int lr = wm + mi * 16 + (lane >> 2);
        #pragma unroll
        for (int cj = 0; cj < 6; cj++) {
            int ng = wn + cj * 8 + (lane & 3) * 2;
            float cc0 = g_catc[b * CATP + n0g + ng];
            float cc1 = g_catc[b * CATP + n0g + ng + 1];
            *(uint32_t*)(sm + lr * EP_STR + ng * 2) =
                f2h2(tanhf(c[mi][cj][0] + cc0), tanhf(c[mi][cj][1] + cc1));
            *(uint32_t*)(sm + (lr + 8) * EP_STR + ng * 2) =
                f2h2(tanhf(c[mi][cj][2] + cc0), tanhf(c[mi][cj][3] + cc1));
        }
    }
    #pragma unroll
    for (int i = 0; i < 3; i++) {
        int idx = t + i * 256;               // < 768
        int r = idx / 24, seg = idx - r * 24;
        *(uint4*)(sm + EP_W2 + r * EP_STR + seg * 16) =
            *(const uint4*)(g_W2H + r * 384 + n0g + seg * 8);
    }
    __syncthreads();

    float c2[2][4];
    #pragma unroll
    for (int j = 0; j < 2; j++)
        #pragma unroll
        for (int q = 0; q < 4; q++) c2[j][q] = 0.f;
    int m0w = (wid & 3) * 16, rb = (wid >> 2) * 16;
    #pragma unroll
    for (int k0 = 0; k0 < 192; k0 += 16) {
        uint32_t aS[4], bW[4];
        ldsm4(aS, sb + (m0w + (lane & 15)) * EP_STR + (k0 + (lane >> 4) * 8) * 2);
        ldsm4(bW, sb + EP_W2 + (rb + (lane & 7) + ((lane >> 4) << 3)) * EP_STR
                      + (k0 + ((lane >> 3) & 1) * 8) * 2);
        mma16816(c2[0], aS, &bW[0]);
        mma16816(c2[1], aS, &bW[2]);
    }
    #pragma unroll
    for (int j = 0; j < 2; j++)
        #pragma unroll
        for (int q = 0; q < 4; q++) {
            int r = rb + j * 8 + (lane & 3) * 2 + (q & 1);
            int md = m0 + m0w + (lane >> 2) + (q >> 1) * 8;
            if (r < RR)
                atomicAdd(&g_s2[((size_t)b * RR + r) * SEQ + (md & 1023)], c2[j][q]);
        }
}

// ======================================================================
// K3: masked softmax; writes A (fp32 out) + probs fp16 (g_AH)
// ======================================================================
__global__ void k3_softmax(const int* __restrict__ len, float* __restrict__ outA) {
    __shared__ float sred[8];
    int br = blockIdx.x;
    int b = br / RR;
    int r = br - b * RR;
    int t = threadIdx.x;
    int lane = t & 31, warp = t >> 5;
    const float* src = g_s2 + (size_t)br * SEQ;
    int L = len[b];

    float4 v = *(const float4*)(src + t * 4);
    float vv[4] = {v.x, v.y, v.z, v.w};
    #pragma unroll
    for (int j = 0; j < 4; j++) if (t * 4 + j >= L) vv[j] = NEGV;

    float mx = fmaxf(fmaxf(vv[0], vv[1]), fmaxf(vv[2], vv[3]));
    #pragma unroll
    for (int o = 16; o; o >>= 1) mx = fmaxf(mx, __shfl_xor_sync(0xffffffffu, mx, o));
    if (lane == 0) sred[warp] = mx;
    __syncthreads();
    mx = sred[0];
    #pragma unroll
    for (int w = 1; w < 8; w++) mx = fmaxf(mx, sred[w]);

    float e[4], s = 0.f;
    #pragma unroll
    for (int j = 0; j < 4; j++) { e[j] = __expf(vv[j] - mx); s += e[j]; }
    #pragma unroll
    for (int o = 16; o; o >>= 1) s += __shfl_xor_sync(0xffffffffu, s, o);
    __syncthreads();
    if (lane == 0) sred[warp] = s;
    __syncthreads();
    s = 0.f;
    #pragma unroll
    for (int w = 0; w < 8; w++) s += sred[w];
    float inv = 1.f / s;

    float p0 = e[0] * inv, p1 = e[1] * inv, p2 = e[2] * inv, p3 = e[3] * inv;
    *(float4*)(outA + (size_t)br * SEQ + t * 4) = make_float4(p0, p1, p2, p3);
    *(uint2*)(g_AH + ((size_t)b * 32 + r) * SEQ + t * 4) =
        make_uint2(f2h2(p0, p1), f2h2(p2, p3));
}

// ======================================================================
// K4: M_enc = A @ enc via fp16 tensor cores; enc fp32 converted on STS.
// ======================================================================
#define K4_ENCSTR 272
#define K4_PRBSTR 80
#define K4_PRB   8704
#define K4_STGSZ 11264

__global__ void __launch_bounds__(256) k4_mgemm(const float* __restrict__ enc) {
    __shared__ __align__(128) char sm4[2 * K4_STGSZ];
    uint32_t sb4 = smem_u32(sm4);
    int t = threadIdx.x;
    int lane = t & 31, wid = t >> 5;
    int dtile = blockIdx.x, b = blockIdx.y;
    const float* Eb = enc + (size_t)b * SEQ * D2 + dtile * 128;
    const __half* Ap = g_AH + ((size_t)b * 32 + (t >> 3)) * SEQ + (t & 7) * 4;

    float c[4][4];
    #pragma unroll
    for (int i = 0; i < 4; i++)
        #pragma unroll
        for (int q = 0; q < 4; q++) c[i][q] = 0.f;

    float4 pe[4];
    uint2 pp = *(const uint2*)(Ap);
    #pragma unroll
    for (int li = 0; li < 4; li++) {
        int idx = t + li * 256;
        pe[li] = *(const float4*)(Eb + (size_t)(idx >> 5) * D2 + (idx & 31) * 4);
    }

    for (int n0 = 0; n0 < SEQ; n0 += 32) {
        int s = (n0 >> 5) & 1;
        uint32_t base = (uint32_t)(s * K4_STGSZ);
        *(uint2*)(sm4 + base + K4_PRB + (t >> 3) * K4_PRBSTR + (t & 7) * 8) = pp;
        #pragma unroll
        for (int li = 0; li < 4; li++) {
            int idx = t + li * 256;
            *(uint2*)(sm4 + base + (idx >> 5) * K4_ENCSTR + (idx & 31) * 8) = cvt4h(pe[li]);
        }
        __syncthreads();
        if (n0 + 32 < SEQ) {
            pp = *(const uint2*)(Ap + n0 + 32);
            #pragma unroll
            for (int li = 0; li < 4; li++) {
                int idx = t + li * 256;
                pe[li] = *(const float4*)(Eb + (size_t)(n0 + 32 + (idx >> 5)) * D2 + (idx & 31) * 4);
            }
        }
        #pragma unroll
        for (int ks = 0; ks < 2; ks++) {
            int kk = ks * 16;
            uint32_t ae[4], bp[8];
            ldsm4t(ae, sb4 + base + (kk + (lane & 7) + ((lane >> 4) << 3)) * K4_ENCSTR
                          + (wid * 16 + ((lane >> 3) & 1) * 8) * 2);
            uint32_t bpr = sb4 + base + K4_PRB
                          + ((lane & 7) + ((lane >> 4) << 3)) * K4_PRBSTR
                          + kk * 2 + ((lane >> 3) & 1) * 16;
            ldsm4(bp, bpr);
            ldsm4(bp + 4, bpr + 16 * K4_PRBSTR);
            mma16816(c[0], ae, &bp[0]);
            mma16816(c[1], ae, &bp[2]);
            mma16816(c[2], ae, &bp[4]);
            mma16816(c[3], ae, &bp[6]);
        }
    }

    #pragma unroll
    for (int nj = 0; nj < 4; nj++)
        #pragma unroll
        for (int q = 0; q < 4; q++) {
            int r = nj * 8 + (lane & 3) * 2 + (q & 1);
            if (r < RR) {
                int d = dtile * 128 + wid * 16 + (lane >> 2) + (q >> 1) * 8;
                g_BM[(size_t)b * KMLP + (size_t)r * D3 + d] = __float2half_rn(c[nj][q]);
            }
        }
}

// ======================================================================
// K5b: fill cat part of BM (exact: softmax rows sum to 1)
// ======================================================================
__global__ void k5b_cat(const float* __restrict__ cat) {
    int idx = (blockIdx.x * 256 + threadIdx.x) * 4;
    int b = idx / (RR * DCAT);
    int rem = idx - b * RR * DCAT;
    int r = rem >> 9, d = rem & 511;
    float4 v = *(const float4*)(cat + (size_t)b * DCAT + d);
    size_t o = (size_t)b * KMLP + (size_t)r * D3 + D2 + d;
    *(uint2*)(g_BM + o) = cvt4h(v);
}

// ======================================================================
// K6: fp16 mma.sync split-K GEMM, double-buffered, 2 CTAs/SM.
// ======================================================================
#define K6_STG 24576
#define K6_W   0
#define K6_B   16384
#define K6_SMEM 49152

__global__ void __launch_bounds__(256, 2) k6_mlp(const float* __restrict__ Wm) {
    extern __shared__ __align__(128) char sm[];
    uint32_t sb = smem_u32(sm);
    int t = threadIdx.x;
    int lane = t & 31, wid = t >> 5;
    int j0 = blockIdx.x * 128;
    int ks = blockIdx.y;
    int kbeg = ks * KCHUNK;
    int wj = (wid >> 2) * 64;
    int wb = (wid & 3) * 16;

    float c[4][2][4];
    #pragma unroll
    for (int i = 0; i < 4; i++)
        #pragma unroll
        for (int j = 0; j < 2; j++)
            #pragma unroll
            for (int q = 0; q < 4; q++) c[i][j][q] = 0.f;

    float4 wreg[8];
    #pragma unroll
    for (int i = 0; i < 2; i++) {
        int idx = t + i * 256;
        int row = idx >> 3, seg = idx & 7;
        uint32_t doff = (uint32_t)(row * 128 + ((seg * 16) ^ ((row & 7) << 4)));
        cpasync16(sb + K6_B + doff, g_BM + (size_t)row * KMLP + kbeg + seg * 8);
    }
    cpcommit();
    #pragma unroll
    for (int li = 0; li < 8; li++) {
        int idx = t + li * 256;
        wreg[li] = *(const float4*)(Wm + (size_t)(j0 + (idx >> 4)) * KMLP + kbeg + (idx & 15) * 4);
    }
    #pragma unroll
    for (int li = 0; li < 8; li++) {
        int idx = t + li * 256;
        int row = idx >> 4, seg = idx & 15;
        uint32_t byte = (uint32_t)(row * 128 + ((seg * 8) ^ ((row & 7) << 4)));
        *(uint2*)(sm + K6_W + byte) = cvt4h(wreg[li]);
    }

    int arow_l = lane & 15;
    int acol_l = (lane >> 4) * 16;
    int brow_l = (lane & 7) + ((lane >> 4) << 3);
    int bcol_l = ((lane >> 3) & 1) * 16;

    for (int cch = 0; cch < NCH6; cch++) {
        int s = cch & 1;
        uint32_t stg = (uint32_t)(s * K6_STG);
        cpwait0();
        __syncthreads();
        if (cch < NCH6 - 1) {
            uint32_t stg1 = (uint32_t)((s ^ 1) * K6_STG);
            int k0n = kbeg + (cch + 1) * 64;
            #pragma unroll
            for (int i = 0; i < 2; i++) {
                int idx = t + i * 256;
                int row = idx >> 3, seg = idx & 7;
                uint32_t doff = (uint32_t)(row * 128 + ((seg * 16) ^ ((row & 7) << 4)));
                cpasync16(sb + stg1 + K6_B + doff, g_BM + (size_t)row * KMLP + k0n + seg * 8);
            }
            cpcommit();
            #pragma unroll
            for (int li = 0; li < 8; li++) {
                int idx = t + li * 256;
                wreg[li] = *(const float4*)(Wm + (size_t)(j0 + (idx >> 4)) * KMLP + k0n + (idx & 15) * 4);
            }
        }
        #pragma unroll
        for (int ksp = 0; ksp < 4; ksp++) {
            int kb = ksp * 32;
            uint32_t ah[4][4], bh[4];
            #pragma unroll
            for (int mi = 0; mi < 4; mi++) {
                int row = wj + mi * 16 + arow_l;
                uint32_t off = (uint32_t)(row * 128 + ((kb + acol_l) ^ ((row & 7) << 4)));
                ldsm4(ah[mi], sb + stg + K6_W + off);
            }
            {
                int row = wb + brow_l;
                uint32_t off = (uint32_t)(row * 128 + ((kb + bcol_l) ^ ((row & 7) << 4)));
                ldsm4(bh, sb + stg + K6_B + off);
            }
            #pragma unroll
            for (int mi = 0; mi < 4; mi++)
                #pragma unroll
                for (int j = 0; j < 2; j++)
                    mma16816(c[mi][j], ah[mi], &bh[j * 2]);
        }
        if (cch < NCH6 - 1) {
            uint32_t stg1 = (uint32_t)((s ^ 1) * K6_STG);
            #pragma unroll
            for (int li = 0; li < 8; li++) {
                int idx = t + li * 256;
                int row = idx >> 4, seg = idx & 15;
                uint32_t byte = (uint32_t)(row * 128 + ((seg * 8) ^ ((row & 7) << 4)));
                *(uint2*)(sm + stg1 + K6_W + byte) = cvt4h(wreg[li]);
            }
        }
    }

    #pragma unroll
    for (int mi = 0; mi < 4; mi++) {
        int jr = j0 + wj + mi * 16 + (lane >> 2);
        #pragma unroll
        for (int j = 0; j < 2; j++) {
            int bc = wb + j * 8 + (lane & 3) * 2;
            float* d0 = g_part + ((size_t)ks * MLPD + jr) * BATCH + bc;
            float* d1 = g_part + ((size_t)ks * MLPD + jr + 8) * BATCH + bc;
            d0[0] = c[mi][j][0]; d0[1] = c[mi][j][1];
            d1[0] = c[mi][j][2]; d1[1] = c[mi][j][3];
        }
    }
}

// ======================================================================
// K7: reduce split-K + bias -> d_out
// ======================================================================
__global__ void k7_reduce(const float* __restrict__ bias, float* __restrict__ out) {
    int idx = blockIdx.x * 256 + threadIdx.x;
    int j = idx >> 6, b = idx & 63;
    float s = bias[j];
    #pragma unroll
    for (int ks = 0; ks < KSPLIT; ks++)
        s += g_part[((size_t)ks * MLPD + j) * BATCH + b];
    out[(size_t)b * MLPD + j] = s;
}

// ======================================================================
extern "C" void kernel_launch(void* const* d_in, const int* in_sizes, int n_in,
                              void* d_out, int out_size) {
    const float* enc = nullptr;
    const int*   len = nullptr;
    const float* cat = nullptr;
    const float* W1 = nullptr;
    const float* W2 = nullptr;
    const float* Wm = nullptr;
    const float* bm = nullptr;
    for (int i = 0; i < n_in; i++) {
        switch (in_sizes[i]) {
            case 67108864: enc = (const float*)d_in[i]; break;
            case 64:       len = (const int*)d_in[i];   break;
            case 32768:    cat = (const float*)d_in[i]; break;
            case 537600:   W1  = (const float*)d_in[i]; break;
            case 10500:    W2  = (const float*)d_in[i]; break;
            case 94371840: Wm  = (const float*)d_in[i]; break;
            case 2048:     bm  = (const float*)d_in[i]; break;
            default: break;
        }
    }
    float* outf = (float*)d_out;
    float* outO = outf;
    float* outA = outf + BATCH * MLPD;

    cudaFuncSetAttribute(k1_s1s2, cudaFuncAttributeMaxDynamicSharedMemorySize, K1_SMEM);
    cudaFuncSetAttribute(k6_mlp, cudaFuncAttributeMaxDynamicSharedMemorySize, K6_SMEM);

    k0_catc   <<<BATCH, 256>>>(W1, cat);
    k0b_w1    <<<(NW1 * D2) / 256, 256>>>(W1);
    k0b2_w2   <<<48, 256>>>(W2);
    k0z_zero  <<<1920, 256>>>();
    k1_s1s2   <<<dim3(2, ROWS / 64), 256, K1_SMEM>>>(enc);
    k3_softmax<<<BATCH * RR, 256>>>(len, outA);
    k4_mgemm  <<<dim3(8, BATCH), 256>>>(enc);
    k5b_cat   <<<(BATCH * RR * DCAT) / 1024, 256>>>(cat);
    k6_mlp    <<<dim3(MLPD / 128, KSPLIT), 256, K6_SMEM>>>(Wm);
    k7_reduce <<<(BATCH * MLPD) / 256, 256>>>(bm, outO);
}